// round 7
// baseline (speedup 1.0000x reference)
#include <cuda_runtime.h>
#include <cuda_bf16.h>
#include <math.h>

#define MAXN 10000
#define MAXE 320000

// ---------------- scratch (device globals; no runtime alloc) ----------------
__device__ float g_s  [MAXN*32];
__device__ float g_v  [MAXN*96];    // (N,3,32)
__device__ float g_scs[MAXN*32];
__device__ float g_scv[MAXN*96];
__device__ float g_xs [MAXN*32];
__device__ float g_xv [MAXN*96];
__device__ float g_aggs[MAXN*64];
__device__ float g_aggv[MAXN*192];
// CSR (by dst) + permuted edge data
__device__ int   g_deg   [MAXN];
__device__ int   g_cursor[MAXN];
__device__ int   g_rowstart[MAXN+1];
__device__ int   g_slot  [MAXE];
__device__ int   g_srcP  [MAXE];
__device__ float g_embP  [MAXE*10];
__device__ float g_YP    [MAXE*3];
// per-edge radial weights, bf16, double-buffered per layer
__device__ __nv_bfloat16 g_wb0[MAXE*128];
__device__ __nv_bfloat16 g_wb1[MAXE*128];

// ---------------- constants ----------------
#define SQRT3F   1.7320508075688772f
#define ISQRT3F  0.5773502691896258f
#define INV_NB   0.17677669529663687f
#define NORM128  0.08838834764831845f
#define NORM256  0.0625f
#define INVS10   0.3162277660168379f
#define C_S      0.3826834323650898f
#define C_X      0.9238795325112867f
#define PI_F     3.14159265358979f
#define WG_TE    128
#define FUSED_SMEM 73728

typedef unsigned long long ull;

// ---------------- packed f32x2 helpers ----------------
__device__ __forceinline__ ull pack2(float lo, float hi) {
    ull r;
    asm("mov.b64 %0, {%1, %2};" : "=l"(r) : "f"(lo), "f"(hi));
    return r;
}
__device__ __forceinline__ void ffma2(ull& acc, ull a, ull b) {
    asm("fma.rn.f32x2 %0, %1, %2, %0;" : "+l"(acc) : "l"(a), "l"(b));
}
__device__ __forceinline__ ull mul2r(ull a, ull b) {
    ull r;
    asm("mul.rn.f32x2 %0, %1, %2;" : "=l"(r) : "l"(a), "l"(b));
    return r;
}
__device__ __forceinline__ void mul2(ull& v, ull s) {
    asm("mul.rn.f32x2 %0, %0, %1;" : "+l"(v) : "l"(s));
}
__device__ __forceinline__ float2 unpack2(ull v) {
    float2 f;
    asm("mov.b64 {%0, %1}, %2;" : "=f"(f.x), "=f"(f.y) : "l"(v));
    return f;
}
__device__ __forceinline__ unsigned int bf16x2_of(float a, float b) {
    unsigned int r;
    asm("cvt.rn.bf16x2.f32 %0, %1, %2;" : "=r"(r) : "f"(b), "f"(a));
    return r;
}

// ---------------- init: unpack nodes + zero degree (fused) ----------------
__global__ void k_init(const float* __restrict__ x, int N) {
    int i = blockIdx.x * blockDim.x + threadIdx.x;
    if (i < N) g_deg[i] = 0;
    if (i >= N*32) return;
    int n = i >> 5, u = i & 31;
    g_s[i] = x[n*128 + u];
    g_v[n*96 +      u] = x[n*128 + 32 + u*3 + 0];
    g_v[n*96 + 32 + u] = x[n*128 + 32 + u*3 + 1];
    g_v[n*96 + 64 + u] = x[n*128 + 32 + u*3 + 2];
}
__global__ void k_hist(const int* __restrict__ edst, int E) {
    int e = blockIdx.x * blockDim.x + threadIdx.x;
    if (e < E) atomicAdd(&g_deg[edst[e]], 1);
}
#define SCAN_T 1024
__global__ void k_scan(int N) {
    __shared__ int sums[SCAN_T];
    int t = threadIdx.x;
    int IT = (N + SCAN_T - 1) / SCAN_T;
    int lo = t * IT, hi = lo + IT; if (hi > N) hi = N; if (lo > N) lo = N;
    int s = 0;
    for (int i = lo; i < hi; i++) s += g_deg[i];
    sums[t] = s;
    __syncthreads();
    for (int off = 1; off < SCAN_T; off <<= 1) {
        int v = (t >= off) ? sums[t - off] : 0;
        __syncthreads();
        sums[t] += v;
        __syncthreads();
    }
    int run = (t == 0) ? 0 : sums[t - 1];
    for (int i = lo; i < hi; i++) {
        g_rowstart[i] = run;
        g_cursor[i]   = run;
        run += g_deg[i];
    }
    if (hi == N) g_rowstart[N] = run;
}
__global__ void k_fill(const int* __restrict__ esrc, const int* __restrict__ edst, int E) {
    int e = blockIdx.x * blockDim.x + threadIdx.x;
    if (e >= E) return;
    int pos = atomicAdd(&g_cursor[edst[e]], 1);
    g_slot[e] = pos;
    g_srcP[pos] = esrc[e];
}

// ---------------- precompute edges (permuted write) ----------------
__global__ void k_pre_edges(const float* __restrict__ evec, int E) {
    int e = blockIdx.x * blockDim.x + threadIdx.x;
    if (e >= E) return;
    int p = g_slot[e];
    float vx = evec[e*3+0], vy = evec[e*3+1], vz = evec[e*3+2];
    float len = sqrtf(vx*vx + vy*vy + vz*vz);
    float inv = 1.0f / (len + 1e-9f);
    g_YP[p*3+0] = SQRT3F * vx * inv;
    g_YP[p*3+1] = SQRT3F * vy * inv;
    g_YP[p*3+2] = SQRT3F * vz * inv;
    float u = 0.5f*len - 2.0f;
    float cut;
    if (u > 0.0f)       cut = 0.0f;
    else if (u < -1.0f) cut = 1.0f;
    else                cut = (1.0f - __cosf(PI_F * u)) * 0.5f;
#pragma unroll
    for (int b = 0; b < 10; b++) {
        float c = (4.0f/9.0f) * (float)b;
        float d = (len - c) * 2.5f;
        g_embP[p*10+b] = __expf(-d*d) * cut;
    }
}

// ================= device bodies ======================

// --- fctp1: packed f32x2, interleaved weight pairs ---
__device__ void fctp1_dev(float* sm, const float* __restrict__ attr,
                          const float* __restrict__ W0, const float* __restrict__ W1,
                          const float* __restrict__ L0, const float* __restrict__ L1,
                          int N, int relBid, int nBlocks) {
    float2* sW02 = (float2*)sm;
    float2* sW12 = (float2*)(sm + 8192);
    for (int i = threadIdx.x; i < 4096; i += 256) {
        sW02[i] = make_float2(W0[i], L0[i]);
        sW12[i] = make_float2(W1[i], L1[i]);
    }
    __syncthreads();
    const ull* w02 = (const ull*)sW02;
    const ull* w12 = (const ull*)sW12;
    int lane = threadIdx.x & 31;
    int wid  = relBid * 8 + (threadIdx.x >> 5);
    int wstr = nBlocks * 8;
    for (int n = wid; n < N; n += wstr) {
        float sl = g_s[n*32 + lane];
        float v0 = g_v[n*96 + lane];
        float v1 = g_v[n*96 + 32 + lane];
        float v2 = g_v[n*96 + 64 + lane];
        ull atp[4];
#pragma unroll
        for (int a = 0; a < 4; a++) { float av = attr[n*4+a]; atp[a] = pack2(av, av); }
        ull accS = 0ull, accV0 = 0ull, accV1 = 0ull, accV2 = 0ull;
        for (int u = 0; u < 32; u++) {
            float su  = __shfl_sync(0xffffffffu, sl, u);
            float vu0 = __shfl_sync(0xffffffffu, v0, u);
            float vu1 = __shfl_sync(0xffffffffu, v1, u);
            float vu2 = __shfl_sync(0xffffffffu, v2, u);
            ull sup = pack2(su, su);
            ull v0p = pack2(vu0, vu0);
            ull v1p = pack2(vu1, vu1);
            ull v2p = pack2(vu2, vu2);
            int base = u*128 + lane;
#pragma unroll
            for (int a = 0; a < 4; a++) {
                int wi = base + a*32;
                ull wa = w02[wi];
                ull wb = w12[wi];
                ffma2(accS,  mul2r(sup, atp[a]), wa);
                ffma2(accV0, mul2r(v0p, atp[a]), wb);
                ffma2(accV1, mul2r(v1p, atp[a]), wb);
                ffma2(accV2, mul2r(v2p, atp[a]), wb);
            }
        }
        float2 fS  = unpack2(accS);
        float2 fV0 = unpack2(accV0);
        float2 fV1 = unpack2(accV1);
        float2 fV2 = unpack2(accV2);
        g_scs[n*32+lane] = fS.x*NORM128;
        g_xs [n*32+lane] = fS.y*NORM128;
        g_scv[n*96+lane]      = fV0.x*NORM128;
        g_scv[n*96+32+lane]   = fV1.x*NORM128;
        g_scv[n*96+64+lane]   = fV2.x*NORM128;
        g_xv [n*96+lane]      = fV0.y*NORM128;
        g_xv [n*96+32+lane]   = fV1.y*NORM128;
        g_xv [n*96+64+lane]   = fV2.y*NORM128;
    }
}

// --- wgemm: h = silu(emb@W1), w = h@W2/8 -> bf16 out ---
__device__ void wgemm_dev(float* sm, const float* __restrict__ Wfc1,
                          const float* __restrict__ Wfc2,
                          __nv_bfloat16* __restrict__ wout, int E, int bid) {
    float* shW1  = sm;
    float* shW2  = sm + 640;
    float* shEmb = sm + 8832;
    float* shH   = sm + 10112;   // stride 65
    int tid = threadIdx.x;
    int eg0 = bid * WG_TE;
    int nE = E - eg0; if (nE > WG_TE) nE = WG_TE;

    for (int i = tid; i < 640; i += 256) shW1[i] = Wfc1[i];
    for (int i = tid; i < 8192; i += 256) shW2[i] = Wfc2[i];
    for (int i = tid; i < WG_TE*10; i += 256) shEmb[i] = (i < nE*10) ? g_embP[eg0*10 + i] : 0.f;
    __syncthreads();

    for (int idx = tid; idx < WG_TE*64; idx += 256) {
        int e = idx >> 6, k = idx & 63;
        float acc = 0.f;
#pragma unroll
        for (int b = 0; b < 10; b++) acc += shEmb[e*10+b] * shW1[b*64+k];
        acc *= INVS10;
        shH[e*65 + k] = acc / (1.0f + __expf(-acc));
    }
    __syncthreads();

    int c0 = (tid & 15) * 8;
    int e0 = (tid >> 4) * 8;
    ull acc[8][4];
#pragma unroll
    for (int e = 0; e < 8; e++)
#pragma unroll
        for (int c = 0; c < 4; c++) acc[e][c] = 0ull;

#pragma unroll 4
    for (int k = 0; k < 64; k++) {
        const ull* Wrow = (const ull*)&shW2[k*128 + c0];
        ull w0 = Wrow[0], w1 = Wrow[1], w2 = Wrow[2], w3 = Wrow[3];
#pragma unroll
        for (int e = 0; e < 8; e++) {
            float hv = shH[(e0+e)*65 + k];
            ull hp = pack2(hv, hv);
            ffma2(acc[e][0], hp, w0);
            ffma2(acc[e][1], hp, w1);
            ffma2(acc[e][2], hp, w2);
            ffma2(acc[e][3], hp, w3);
        }
    }

    ull sc = pack2(0.125f, 0.125f);
#pragma unroll
    for (int e = 0; e < 8; e++) {
        int ge = eg0 + e0 + e;
        if (ge >= E) break;
        mul2(acc[e][0], sc); mul2(acc[e][1], sc);
        mul2(acc[e][2], sc); mul2(acc[e][3], sc);
        float2 f0 = unpack2(acc[e][0]);
        float2 f1 = unpack2(acc[e][1]);
        float2 f2 = unpack2(acc[e][2]);
        float2 f3 = unpack2(acc[e][3]);
        uint4 pk;
        pk.x = bf16x2_of(f0.x, f0.y);
        pk.y = bf16x2_of(f1.x, f1.y);
        pk.z = bf16x2_of(f2.x, f2.y);
        pk.w = bf16x2_of(f3.x, f3.y);
        *(uint4*)&wout[ge*128 + c0] = pk;
    }
}

// --- fctp2: packed f32x2 + gated state update ---
__device__ void fctp2_dev(float* sm, const float* __restrict__ attr,
                          const float* __restrict__ W20, const float* __restrict__ W21,
                          int N, int relBid, int nBlocks) {
    float2* sWp = (float2*)sm;
    for (int i = threadIdx.x; i < 8192; i += 256)
        sWp[i] = make_float2(W20[i], W21[i]);
    __syncthreads();
    const ull* wPair = (const ull*)sWp;
    int lane = threadIdx.x & 31;
    int wid  = relBid * 8 + (threadIdx.x >> 5);
    int wstr = nBlocks * 8;
    for (int n = wid; n < N; n += wstr) {
        float sa  = g_aggs[n*64 + lane],        sb  = g_aggs[n*64 + 32 + lane];
        float va0 = g_aggv[n*192 + lane],       vb0 = g_aggv[n*192 + 32 + lane];
        float va1 = g_aggv[n*192 + 64 + lane],  vb1 = g_aggv[n*192 + 96 + lane];
        float va2 = g_aggv[n*192 + 128 + lane], vb2 = g_aggv[n*192 + 160 + lane];
        ull atp[4];
#pragma unroll
        for (int a = 0; a < 4; a++) { float av = attr[n*4+a]; atp[a] = pack2(av, av); }
        ull accA = 0ull;   // {os, ov2}
        ull accB = 0ull;   // {ov0, ov1}
#pragma unroll 1
        for (int half = 0; half < 2; half++) {
            float ss  = half ? sb  : sa;
            float vv0 = half ? vb0 : va0;
            float vv1 = half ? vb1 : va1;
            float vv2 = half ? vb2 : va2;
            int uoff = half ? 32 : 0;
            for (int u = 0; u < 32; u++) {
                float su = __shfl_sync(0xffffffffu, ss,  u);
                float w0 = __shfl_sync(0xffffffffu, vv0, u);
                float w1 = __shfl_sync(0xffffffffu, vv1, u);
                float w2 = __shfl_sync(0xffffffffu, vv2, u);
                ull pA = pack2(su, w2);
                ull pB = pack2(w0, w1);
                int base = (u + uoff)*128 + lane;
#pragma unroll
                for (int a = 0; a < 4; a++) {
                    int wi = base + a*32;
                    ull wp = wPair[wi];
                    float2 wf = unpack2(wp);
                    ull wdup = pack2(wf.y, wf.y);
                    ffma2(accA, mul2r(pA, atp[a]), wp);
                    ffma2(accB, mul2r(pB, atp[a]), wdup);
                }
            }
        }
        float2 fA = unpack2(accA);
        float2 fB = unpack2(accB);
        float os  = fA.x*NORM256, ov2 = fA.y*NORM256;
        float ov0 = fB.x*NORM256, ov1 = fB.y*NORM256;
        float sn  = C_S * g_scs[n*32+lane] + C_X * os;
        float sig = 1.0f / (1.0f + __expf(-sn));
        g_s[n*32+lane] += sn * sig;
        float vn0 = C_S * g_scv[n*96+lane]      + C_X * ov0;
        float vn1 = C_S * g_scv[n*96+32+lane]   + C_X * ov1;
        float vn2 = C_S * g_scv[n*96+64+lane]   + C_X * ov2;
        g_v[n*96+lane]      += vn0 * sig;
        g_v[n*96+32+lane]   += vn1 * sig;
        g_v[n*96+64+lane]   += vn2 * sig;
    }
}

// ================= gather: dedup feature loads ======================
// warp 0  : loads xs[src] once -> k0 (w[u]) and k2 (w[64+u] * Y)
// warp 1-3: component i=grp-1, loads xv_i[src] once -> k3 (w[96+u]) and
//           k1 partial (w[32+u]*Y_i*xv_i), reduced across warps via smem.
template<int BUF>
__global__ void __launch_bounds__(256)
k_gather(int N) {
    const __nv_bfloat16* __restrict__ win = BUF ? g_wb1 : g_wb0;
    __shared__ float shred[2][96];
    int tid = threadIdx.x;
    int half = tid >> 7;
    int sub  = tid & 127;
    int grp = sub >> 5, u = sub & 31;
    int n = blockIdx.x*2 + half;
    bool valid = (n < N);
    int t0 = 0, t1 = 0;
    if (valid) { t0 = g_rowstart[n]; t1 = g_rowstart[n+1]; }

    if (grp == 0) {
        float a0 = 0.f, b0 = 0.f;
        float m0 = 0.f, m1 = 0.f, m2 = 0.f;
        int e = t0;
        for (; e + 2 <= t1; e += 2) {
            int s0 = g_srcP[e], s1 = g_srcP[e+1];
            float w0a = __bfloat162float(win[(e+0)*128 + u]);
            float w0b = __bfloat162float(win[(e+1)*128 + u]);
            float w2a = __bfloat162float(win[(e+0)*128 + 64 + u]);
            float w2b = __bfloat162float(win[(e+1)*128 + 64 + u]);
            float xsa = g_xs[s0*32 + u];
            float xsb = g_xs[s1*32 + u];
            a0 += w0a * xsa;
            b0 += w0b * xsb;
            float ma = w2a * xsa;
            float mb = w2b * xsb;
            m0 += ma * g_YP[e*3+0] + mb * g_YP[e*3+3];
            m1 += ma * g_YP[e*3+1] + mb * g_YP[e*3+4];
            m2 += ma * g_YP[e*3+2] + mb * g_YP[e*3+5];
        }
        for (; e < t1; e++) {
            int s0 = g_srcP[e];
            float xsa = g_xs[s0*32 + u];
            a0 += __bfloat162float(win[e*128 + u]) * xsa;
            float ma = __bfloat162float(win[e*128 + 64 + u]) * xsa;
            m0 += ma * g_YP[e*3+0];
            m1 += ma * g_YP[e*3+1];
            m2 += ma * g_YP[e*3+2];
        }
        if (valid) {
            g_aggs[n*64 + u]        = (a0 + b0) * INV_NB;
            g_aggv[n*192 +       u] = m0 * INV_NB;
            g_aggv[n*192 +  64 + u] = m1 * INV_NB;
            g_aggv[n*192 + 128 + u] = m2 * INV_NB;
        }
    } else {
        int i = grp - 1;
        float ak1 = 0.f, bk1 = 0.f, ak3 = 0.f, bk3 = 0.f;
        int e = t0;
        for (; e + 2 <= t1; e += 2) {
            int s0 = g_srcP[e], s1 = g_srcP[e+1];
            float w1a = __bfloat162float(win[(e+0)*128 + 32 + u]);
            float w1b = __bfloat162float(win[(e+1)*128 + 32 + u]);
            float w3a = __bfloat162float(win[(e+0)*128 + 96 + u]);
            float w3b = __bfloat162float(win[(e+1)*128 + 96 + u]);
            float xva = g_xv[s0*96 + i*32 + u];
            float xvb = g_xv[s1*96 + i*32 + u];
            ak3 += w3a * xva;
            bk3 += w3b * xvb;
            ak1 += (w1a * g_YP[e*3 + i])     * xva;
            bk1 += (w1b * g_YP[e*3 + 3 + i]) * xvb;
        }
        for (; e < t1; e++) {
            int s0 = g_srcP[e];
            float xva = g_xv[s0*96 + i*32 + u];
            ak3 += __bfloat162float(win[e*128 + 96 + u]) * xva;
            ak1 += (__bfloat162float(win[e*128 + 32 + u]) * g_YP[e*3 + i]) * xva;
        }
        if (valid)
            g_aggv[n*192 + 32 + i*64 + u] = (ak3 + bk3) * INV_NB;
        shred[half][i*32 + u] = ak1 + bk1;
    }
    __syncthreads();
    if (valid && grp == 1) {
        float s = shred[half][u] + shred[half][32 + u] + shred[half][64 + u];
        g_aggs[n*64 + 32 + u] = s * ISQRT3F * INV_NB;
    }
}

// ================= launches ======================

// A: wgemm(L0)->wb0 || fctp1(L0)
__global__ void __launch_bounds__(256)
k_fusedA(const float* __restrict__ attr,
         const float* __restrict__ W0, const float* __restrict__ W1,
         const float* __restrict__ L0, const float* __restrict__ L1,
         const float* __restrict__ Wfc1, const float* __restrict__ Wfc2,
         int N, int E, int nWG, int nFC) {
    extern __shared__ float sm[];
    if ((int)blockIdx.x < nWG) wgemm_dev(sm, Wfc1, Wfc2, g_wb0, E, blockIdx.x);
    else fctp1_dev(sm, attr, W0, W1, L0, L1, N, blockIdx.x - nWG, nFC);
}

// C: wgemm(L1)->wb1 || fctp2(L0)
__global__ void __launch_bounds__(256)
k_fusedC(const float* __restrict__ attr,
         const float* __restrict__ W20, const float* __restrict__ W21,
         const float* __restrict__ Wfc1, const float* __restrict__ Wfc2,
         int N, int E, int nWG, int nFC) {
    extern __shared__ float sm[];
    if ((int)blockIdx.x < nWG) wgemm_dev(sm, Wfc1, Wfc2, g_wb1, E, blockIdx.x);
    else fctp2_dev(sm, attr, W20, W21, N, blockIdx.x - nWG, nFC);
}

__global__ void __launch_bounds__(256)
k_fctp1(const float* __restrict__ attr,
        const float* __restrict__ W0, const float* __restrict__ W1,
        const float* __restrict__ L0, const float* __restrict__ L1, int N) {
    extern __shared__ float sm[];
    fctp1_dev(sm, attr, W0, W1, L0, L1, N, blockIdx.x, gridDim.x);
}

__global__ void __launch_bounds__(256)
k_fctp2(const float* __restrict__ attr,
        const float* __restrict__ W20, const float* __restrict__ W21, int N) {
    extern __shared__ float sm[];
    fctp2_dev(sm, attr, W20, W21, N, blockIdx.x, gridDim.x);
}

// ---------------- readout + pooling ----------------
__global__ void k_zero_out(float* out) { out[threadIdx.x] = 0.0f; }

__global__ void k_read(const float* __restrict__ attr, const int* __restrict__ batch,
                       const float* __restrict__ Wread, float* __restrict__ out,
                       int N, float poolscale) {
    __shared__ float shW[2048];
    __shared__ float pool[128];
    for (int i = threadIdx.x; i < 2048; i += blockDim.x) shW[i] = Wread[i];
    if (threadIdx.x < 128) pool[threadIdx.x] = 0.0f;
    __syncthreads();
    int lane = threadIdx.x & 31;
    int wid  = blockIdx.x * (blockDim.x >> 5) + (threadIdx.x >> 5);
    int wstr = gridDim.x * (blockDim.x >> 5);
    int w = lane & 15;
    for (int n = wid; n < N; n += wstr) {
        float sl = g_s[n*32 + lane];
        float at[4] = {attr[n*4+0], attr[n*4+1], attr[n*4+2], attr[n*4+3]};
        float acc = 0.f;
        for (int u = 0; u < 32; u++) {
            float su = __shfl_sync(0xffffffffu, sl, u);
            int base = u*64 + w;
#pragma unroll
            for (int a = 0; a < 4; a++) acc += su*at[a]*shW[base + a*16];
        }
        if (lane < 16) {
            int g = batch[n];
            atomicAdd(&pool[g*16 + w], acc * NORM128 * poolscale);
        }
    }
    __syncthreads();
    if (threadIdx.x < 128) atomicAdd(&out[threadIdx.x], pool[threadIdx.x]);
}

// ---------------- launcher ----------------
extern "C" void kernel_launch(void* const* d_in, const int* in_sizes, int n_in,
                              void* d_out, int out_size) {
    const float* x    = (const float*)d_in[0];
    const float* attr = (const float*)d_in[1];
    const float* evec = (const float*)d_in[2];
    const int*   batch= (const int*)  d_in[3];
    const int*   esrc = (const int*)  d_in[4];
    const int*   edst = (const int*)  d_in[5];
    const float* Wsc0 = (const float*)d_in[6];
    const float* Wsc1 = (const float*)d_in[7];
    const float* Wl10 = (const float*)d_in[8];
    const float* Wl11 = (const float*)d_in[9];
    const float* Wfc1 = (const float*)d_in[10];
    const float* Wfc2 = (const float*)d_in[11];
    const float* Wl20 = (const float*)d_in[12];
    const float* Wl21 = (const float*)d_in[13];
    const float* Wread= (const float*)d_in[14];
    int N = in_sizes[0] / 128;
    int E = in_sizes[4];

    cudaFuncSetAttribute(k_fusedA, cudaFuncAttributeMaxDynamicSharedMemorySize, FUSED_SMEM);
    cudaFuncSetAttribute(k_fusedC, cudaFuncAttributeMaxDynamicSharedMemorySize, FUSED_SMEM);
    cudaFuncSetAttribute(k_fctp1,  cudaFuncAttributeMaxDynamicSharedMemorySize, 65536);
    cudaFuncSetAttribute(k_fctp2,  cudaFuncAttributeMaxDynamicSharedMemorySize, 65536);

    // init + CSR build (by dst) + permuted precompute
    k_init<<<(N*32 + 255) / 256, 256>>>(x, N);
    k_hist<<<(E + 255) / 256, 256>>>(edst, E);
    k_scan<<<1, SCAN_T>>>(N);
    k_fill<<<(E + 255) / 256, 256>>>(esrc, edst, E);
    k_pre_edges<<<(E + 255) / 256, 256>>>(evec, E);

    int nWG = (E + WG_TE - 1) / WG_TE;
    int nFC = 444;
    int nGB = (N + 1) / 2;

    // layer 0 + overlapped wgemm(L1)
    k_fusedA<<<nWG + nFC, 256, FUSED_SMEM>>>(attr, Wsc0, Wsc1, Wl10, Wl11,
                                             Wfc1, Wfc2, N, E, nWG, nFC);
    k_gather<0><<<nGB, 256>>>(N);
    k_fusedC<<<nWG + nFC, 256, FUSED_SMEM>>>(attr, Wl20, Wl21,
                                             Wfc1 + 640, Wfc2 + 8192, N, E, nWG, nFC);
    // layer 1 (wgemm already done -> wb1)
    k_fctp1<<<444, 256, 65536>>>(attr, Wsc0 + 4096, Wsc1 + 4096,
                                 Wl10 + 4096, Wl11 + 4096, N);
    k_gather<1><<<nGB, 256>>>(N);
    k_fctp2<<<444, 256, 65536>>>(attr, Wl20 + 8192, Wl21 + 8192, N);

    k_zero_out<<<1, 128>>>((float*)d_out);
    float poolscale = 1.0f / sqrtf((float)N / 8.0f);
    k_read<<<592, 128>>>(attr, batch, Wread, (float*)d_out, N, poolscale);
}

// round 8
// speedup vs baseline: 1.0141x; 1.0141x over previous
#include <cuda_runtime.h>
#include <cuda_bf16.h>
#include <math.h>

#define MAXN 10000
#define MAXE 320000

// ---------------- scratch (device globals; no runtime alloc) ----------------
__device__ float g_s  [MAXN*32];
__device__ float g_v  [MAXN*96];    // (N,3,32)
__device__ float g_scs[MAXN*32];
__device__ float g_scv[MAXN*96];
__device__ float g_xs [MAXN*32];
__device__ float g_xv [MAXN*96];
__device__ float g_aggs[MAXN*64];
__device__ float g_aggv[MAXN*192];
// CSR (by dst) + permuted edge data
__device__ int   g_deg   [MAXN];
__device__ int   g_cursor[MAXN];
__device__ int   g_rowstart[MAXN+1];
__device__ int   g_slot  [MAXE];
__device__ int   g_srcP  [MAXE];
__device__ float g_embP  [MAXE*10];
__device__ float g_YP    [MAXE*3];
// per-edge radial weights, bf16, double-buffered per layer
__device__ __nv_bfloat16 g_wb0[MAXE*128];
__device__ __nv_bfloat16 g_wb1[MAXE*128];

// ---------------- constants ----------------
#define SQRT3F   1.7320508075688772f
#define ISQRT3F  0.5773502691896258f
#define INV_NB   0.17677669529663687f
#define NORM128  0.08838834764831845f
#define NORM256  0.0625f
#define INVS10   0.3162277660168379f
#define C_S      0.3826834323650898f
#define C_X      0.9238795325112867f
#define PI_F     3.14159265358979f
#define WG_TE    128
#define FUSED_SMEM 73728

typedef unsigned long long ull;

// ---------------- packed f32x2 helpers ----------------
__device__ __forceinline__ ull pack2(float lo, float hi) {
    ull r;
    asm("mov.b64 %0, {%1, %2};" : "=l"(r) : "f"(lo), "f"(hi));
    return r;
}
__device__ __forceinline__ void ffma2(ull& acc, ull a, ull b) {
    asm("fma.rn.f32x2 %0, %1, %2, %0;" : "+l"(acc) : "l"(a), "l"(b));
}
__device__ __forceinline__ ull mul2r(ull a, ull b) {
    ull r;
    asm("mul.rn.f32x2 %0, %1, %2;" : "=l"(r) : "l"(a), "l"(b));
    return r;
}
__device__ __forceinline__ void mul2(ull& v, ull s) {
    asm("mul.rn.f32x2 %0, %0, %1;" : "+l"(v) : "l"(s));
}
__device__ __forceinline__ float2 unpack2(ull v) {
    float2 f;
    asm("mov.b64 {%0, %1}, %2;" : "=f"(f.x), "=f"(f.y) : "l"(v));
    return f;
}
__device__ __forceinline__ unsigned int bf16x2_of(float a, float b) {
    unsigned int r;
    asm("cvt.rn.bf16x2.f32 %0, %1, %2;" : "=r"(r) : "f"(b), "f"(a));
    return r;
}
// streaming bf16 load (evict-first: don't pollute L2 with the w stream)
__device__ __forceinline__ float ldcs_bf16(const __nv_bfloat16* p) {
    unsigned short v;
    asm("ld.global.cs.u16 %0, [%1];" : "=h"(v) : "l"(p));
    __nv_bfloat16 b;
    *reinterpret_cast<unsigned short*>(&b) = v;
    return __bfloat162float(b);
}

// ---------------- init: unpack nodes + zero degree (fused) ----------------
__global__ void k_init(const float* __restrict__ x, int N) {
    int i = blockIdx.x * blockDim.x + threadIdx.x;
    if (i < N) g_deg[i] = 0;
    if (i >= N*32) return;
    int n = i >> 5, u = i & 31;
    g_s[i] = x[n*128 + u];
    g_v[n*96 +      u] = x[n*128 + 32 + u*3 + 0];
    g_v[n*96 + 32 + u] = x[n*128 + 32 + u*3 + 1];
    g_v[n*96 + 64 + u] = x[n*128 + 32 + u*3 + 2];
}
__global__ void k_hist(const int* __restrict__ edst, int E) {
    int e = blockIdx.x * blockDim.x + threadIdx.x;
    if (e < E) atomicAdd(&g_deg[edst[e]], 1);
}
#define SCAN_T 1024
__global__ void k_scan(int N) {
    __shared__ int sums[SCAN_T];
    int t = threadIdx.x;
    int IT = (N + SCAN_T - 1) / SCAN_T;
    int lo = t * IT, hi = lo + IT; if (hi > N) hi = N; if (lo > N) lo = N;
    int s = 0;
    for (int i = lo; i < hi; i++) s += g_deg[i];
    sums[t] = s;
    __syncthreads();
    for (int off = 1; off < SCAN_T; off <<= 1) {
        int v = (t >= off) ? sums[t - off] : 0;
        __syncthreads();
        sums[t] += v;
        __syncthreads();
    }
    int run = (t == 0) ? 0 : sums[t - 1];
    for (int i = lo; i < hi; i++) {
        g_rowstart[i] = run;
        g_cursor[i]   = run;
        run += g_deg[i];
    }
    if (hi == N) g_rowstart[N] = run;
}
__global__ void k_fill(const int* __restrict__ esrc, const int* __restrict__ edst, int E) {
    int e = blockIdx.x * blockDim.x + threadIdx.x;
    if (e >= E) return;
    int pos = atomicAdd(&g_cursor[edst[e]], 1);
    g_slot[e] = pos;
    g_srcP[pos] = esrc[e];
}

// ---------------- precompute edges (permuted write) ----------------
__global__ void k_pre_edges(const float* __restrict__ evec, int E) {
    int e = blockIdx.x * blockDim.x + threadIdx.x;
    if (e >= E) return;
    int p = g_slot[e];
    float vx = evec[e*3+0], vy = evec[e*3+1], vz = evec[e*3+2];
    float len = sqrtf(vx*vx + vy*vy + vz*vz);
    float inv = 1.0f / (len + 1e-9f);
    g_YP[p*3+0] = SQRT3F * vx * inv;
    g_YP[p*3+1] = SQRT3F * vy * inv;
    g_YP[p*3+2] = SQRT3F * vz * inv;
    float u = 0.5f*len - 2.0f;
    float cut;
    if (u > 0.0f)       cut = 0.0f;
    else if (u < -1.0f) cut = 1.0f;
    else                cut = (1.0f - __cosf(PI_F * u)) * 0.5f;
#pragma unroll
    for (int b = 0; b < 10; b++) {
        float c = (4.0f/9.0f) * (float)b;
        float d = (len - c) * 2.5f;
        g_embP[p*10+b] = __expf(-d*d) * cut;
    }
}

// ================= device bodies ======================

// --- fctp1: packed f32x2, interleaved weight pairs ---
__device__ void fctp1_dev(float* sm, const float* __restrict__ attr,
                          const float* __restrict__ W0, const float* __restrict__ W1,
                          const float* __restrict__ L0, const float* __restrict__ L1,
                          int N, int relBid, int nBlocks) {
    float2* sW02 = (float2*)sm;
    float2* sW12 = (float2*)(sm + 8192);
    for (int i = threadIdx.x; i < 4096; i += 256) {
        sW02[i] = make_float2(W0[i], L0[i]);
        sW12[i] = make_float2(W1[i], L1[i]);
    }
    __syncthreads();
    const ull* w02 = (const ull*)sW02;
    const ull* w12 = (const ull*)sW12;
    int lane = threadIdx.x & 31;
    int wid  = relBid * 8 + (threadIdx.x >> 5);
    int wstr = nBlocks * 8;
    for (int n = wid; n < N; n += wstr) {
        float sl = g_s[n*32 + lane];
        float v0 = g_v[n*96 + lane];
        float v1 = g_v[n*96 + 32 + lane];
        float v2 = g_v[n*96 + 64 + lane];
        ull atp[4];
#pragma unroll
        for (int a = 0; a < 4; a++) { float av = attr[n*4+a]; atp[a] = pack2(av, av); }
        ull accS = 0ull, accV0 = 0ull, accV1 = 0ull, accV2 = 0ull;
        for (int u = 0; u < 32; u++) {
            float su  = __shfl_sync(0xffffffffu, sl, u);
            float vu0 = __shfl_sync(0xffffffffu, v0, u);
            float vu1 = __shfl_sync(0xffffffffu, v1, u);
            float vu2 = __shfl_sync(0xffffffffu, v2, u);
            ull sup = pack2(su, su);
            ull v0p = pack2(vu0, vu0);
            ull v1p = pack2(vu1, vu1);
            ull v2p = pack2(vu2, vu2);
            int base = u*128 + lane;
#pragma unroll
            for (int a = 0; a < 4; a++) {
                int wi = base + a*32;
                ull wa = w02[wi];
                ull wb = w12[wi];
                ffma2(accS,  mul2r(sup, atp[a]), wa);
                ffma2(accV0, mul2r(v0p, atp[a]), wb);
                ffma2(accV1, mul2r(v1p, atp[a]), wb);
                ffma2(accV2, mul2r(v2p, atp[a]), wb);
            }
        }
        float2 fS  = unpack2(accS);
        float2 fV0 = unpack2(accV0);
        float2 fV1 = unpack2(accV1);
        float2 fV2 = unpack2(accV2);
        g_scs[n*32+lane] = fS.x*NORM128;
        g_xs [n*32+lane] = fS.y*NORM128;
        g_scv[n*96+lane]      = fV0.x*NORM128;
        g_scv[n*96+32+lane]   = fV1.x*NORM128;
        g_scv[n*96+64+lane]   = fV2.x*NORM128;
        g_xv [n*96+lane]      = fV0.y*NORM128;
        g_xv [n*96+32+lane]   = fV1.y*NORM128;
        g_xv [n*96+64+lane]   = fV2.y*NORM128;
    }
}

// --- wgemm: h = silu(emb@W1), w = h@W2/8 -> bf16 out ---
__device__ void wgemm_dev(float* sm, const float* __restrict__ Wfc1,
                          const float* __restrict__ Wfc2,
                          __nv_bfloat16* __restrict__ wout, int E, int bid) {
    float* shW1  = sm;
    float* shW2  = sm + 640;
    float* shEmb = sm + 8832;
    float* shH   = sm + 10112;   // stride 65
    int tid = threadIdx.x;
    int eg0 = bid * WG_TE;
    int nE = E - eg0; if (nE > WG_TE) nE = WG_TE;

    for (int i = tid; i < 640; i += 256) shW1[i] = Wfc1[i];
    for (int i = tid; i < 8192; i += 256) shW2[i] = Wfc2[i];
    for (int i = tid; i < WG_TE*10; i += 256) shEmb[i] = (i < nE*10) ? g_embP[eg0*10 + i] : 0.f;
    __syncthreads();

    for (int idx = tid; idx < WG_TE*64; idx += 256) {
        int e = idx >> 6, k = idx & 63;
        float acc = 0.f;
#pragma unroll
        for (int b = 0; b < 10; b++) acc += shEmb[e*10+b] * shW1[b*64+k];
        acc *= INVS10;
        shH[e*65 + k] = acc / (1.0f + __expf(-acc));
    }
    __syncthreads();

    int c0 = (tid & 15) * 8;
    int e0 = (tid >> 4) * 8;
    ull acc[8][4];
#pragma unroll
    for (int e = 0; e < 8; e++)
#pragma unroll
        for (int c = 0; c < 4; c++) acc[e][c] = 0ull;

#pragma unroll 4
    for (int k = 0; k < 64; k++) {
        const ull* Wrow = (const ull*)&shW2[k*128 + c0];
        ull w0 = Wrow[0], w1 = Wrow[1], w2 = Wrow[2], w3 = Wrow[3];
#pragma unroll
        for (int e = 0; e < 8; e++) {
            float hv = shH[(e0+e)*65 + k];
            ull hp = pack2(hv, hv);
            ffma2(acc[e][0], hp, w0);
            ffma2(acc[e][1], hp, w1);
            ffma2(acc[e][2], hp, w2);
            ffma2(acc[e][3], hp, w3);
        }
    }

    ull sc = pack2(0.125f, 0.125f);
#pragma unroll
    for (int e = 0; e < 8; e++) {
        int ge = eg0 + e0 + e;
        if (ge >= E) break;
        mul2(acc[e][0], sc); mul2(acc[e][1], sc);
        mul2(acc[e][2], sc); mul2(acc[e][3], sc);
        float2 f0 = unpack2(acc[e][0]);
        float2 f1 = unpack2(acc[e][1]);
        float2 f2 = unpack2(acc[e][2]);
        float2 f3 = unpack2(acc[e][3]);
        uint4 pk;
        pk.x = bf16x2_of(f0.x, f0.y);
        pk.y = bf16x2_of(f1.x, f1.y);
        pk.z = bf16x2_of(f2.x, f2.y);
        pk.w = bf16x2_of(f3.x, f3.y);
        *(uint4*)&wout[ge*128 + c0] = pk;
    }
}

// --- fctp2: packed f32x2 + gated state update ---
__device__ void fctp2_dev(float* sm, const float* __restrict__ attr,
                          const float* __restrict__ W20, const float* __restrict__ W21,
                          int N, int relBid, int nBlocks) {
    float2* sWp = (float2*)sm;
    for (int i = threadIdx.x; i < 8192; i += 256)
        sWp[i] = make_float2(W20[i], W21[i]);
    __syncthreads();
    const ull* wPair = (const ull*)sWp;
    int lane = threadIdx.x & 31;
    int wid  = relBid * 8 + (threadIdx.x >> 5);
    int wstr = nBlocks * 8;
    for (int n = wid; n < N; n += wstr) {
        float sa  = g_aggs[n*64 + lane],        sb  = g_aggs[n*64 + 32 + lane];
        float va0 = g_aggv[n*192 + lane],       vb0 = g_aggv[n*192 + 32 + lane];
        float va1 = g_aggv[n*192 + 64 + lane],  vb1 = g_aggv[n*192 + 96 + lane];
        float va2 = g_aggv[n*192 + 128 + lane], vb2 = g_aggv[n*192 + 160 + lane];
        ull atp[4];
#pragma unroll
        for (int a = 0; a < 4; a++) { float av = attr[n*4+a]; atp[a] = pack2(av, av); }
        ull accA = 0ull;   // {os, ov2}
        ull accB = 0ull;   // {ov0, ov1}
#pragma unroll 1
        for (int half = 0; half < 2; half++) {
            float ss  = half ? sb  : sa;
            float vv0 = half ? vb0 : va0;
            float vv1 = half ? vb1 : va1;
            float vv2 = half ? vb2 : va2;
            int uoff = half ? 32 : 0;
            for (int u = 0; u < 32; u++) {
                float su = __shfl_sync(0xffffffffu, ss,  u);
                float w0 = __shfl_sync(0xffffffffu, vv0, u);
                float w1 = __shfl_sync(0xffffffffu, vv1, u);
                float w2 = __shfl_sync(0xffffffffu, vv2, u);
                ull pA = pack2(su, w2);
                ull pB = pack2(w0, w1);
                int base = (u + uoff)*128 + lane;
#pragma unroll
                for (int a = 0; a < 4; a++) {
                    int wi = base + a*32;
                    ull wp = wPair[wi];
                    float2 wf = unpack2(wp);
                    ull wdup = pack2(wf.y, wf.y);
                    ffma2(accA, mul2r(pA, atp[a]), wp);
                    ffma2(accB, mul2r(pB, atp[a]), wdup);
                }
            }
        }
        float2 fA = unpack2(accA);
        float2 fB = unpack2(accB);
        float os  = fA.x*NORM256, ov2 = fA.y*NORM256;
        float ov0 = fB.x*NORM256, ov1 = fB.y*NORM256;
        float sn  = C_S * g_scs[n*32+lane] + C_X * os;
        float sig = 1.0f / (1.0f + __expf(-sn));
        g_s[n*32+lane] += sn * sig;
        float vn0 = C_S * g_scv[n*96+lane]      + C_X * ov0;
        float vn1 = C_S * g_scv[n*96+32+lane]   + C_X * ov1;
        float vn2 = C_S * g_scv[n*96+64+lane]   + C_X * ov2;
        g_v[n*96+lane]      += vn0 * sig;
        g_v[n*96+32+lane]   += vn1 * sig;
        g_v[n*96+64+lane]   += vn2 * sig;
    }
}

// ================= gather: warp-staged indices, no index->feature chain =====
// warp k of each 128-thread group handles one message slot; edge indices and
// Y are staged per-lane, extracted via shuffle -> feature loads are
// independent across unrolled iterations.
template<int BUF>
__global__ void __launch_bounds__(256)
k_gather(int N) {
    const __nv_bfloat16* __restrict__ win = BUF ? g_wb1 : g_wb0;
    int tid = threadIdx.x;
    int n = blockIdx.x*2 + (tid >> 7);
    if (n >= N) return;
    int sub = tid & 127;
    int k = sub >> 5, u = sub & 31;
    int t0 = g_rowstart[n], t1 = g_rowstart[n+1];
    const unsigned FULL = 0xffffffffu;
    float a0 = 0.f, a1 = 0.f, a2 = 0.f;

    for (int base = t0; base < t1; base += 32) {
        int eIdx = base + u;
        bool has = (eIdx < t1);
        int myS = has ? g_srcP[eIdx] : 0;
        float myY0 = 0.f, myY1 = 0.f, myY2 = 0.f;
        if (k == 1 || k == 2) {
            if (has) {
                myY0 = g_YP[eIdx*3+0];
                myY1 = g_YP[eIdx*3+1];
                myY2 = g_YP[eIdx*3+2];
            }
        }
        int nT = t1 - base; if (nT > 32) nT = 32;

        if (k == 0) {
#pragma unroll 4
            for (int e = 0; e < nT; e++) {
                int src = __shfl_sync(FULL, myS, e);
                float w = ldcs_bf16(&win[(size_t)(base+e)*128 + u]);
                a0 += w * __ldg(&g_xs[src*32 + u]);
            }
        } else if (k == 1) {
#pragma unroll 4
            for (int e = 0; e < nT; e++) {
                int src = __shfl_sync(FULL, myS, e);
                float Y0 = __shfl_sync(FULL, myY0, e);
                float Y1 = __shfl_sync(FULL, myY1, e);
                float Y2 = __shfl_sync(FULL, myY2, e);
                float w = ldcs_bf16(&win[(size_t)(base+e)*128 + 32 + u]);
                float d = Y0 * __ldg(&g_xv[src*96 + u])
                        + Y1 * __ldg(&g_xv[src*96 + 32 + u])
                        + Y2 * __ldg(&g_xv[src*96 + 64 + u]);
                a0 += w * d;
            }
        } else if (k == 2) {
#pragma unroll 4
            for (int e = 0; e < nT; e++) {
                int src = __shfl_sync(FULL, myS, e);
                float Y0 = __shfl_sync(FULL, myY0, e);
                float Y1 = __shfl_sync(FULL, myY1, e);
                float Y2 = __shfl_sync(FULL, myY2, e);
                float w = ldcs_bf16(&win[(size_t)(base+e)*128 + 64 + u]);
                float m = w * __ldg(&g_xs[src*32 + u]);
                a0 += m * Y0;
                a1 += m * Y1;
                a2 += m * Y2;
            }
        } else {
#pragma unroll 4
            for (int e = 0; e < nT; e++) {
                int src = __shfl_sync(FULL, myS, e);
                float w = ldcs_bf16(&win[(size_t)(base+e)*128 + 96 + u]);
                a0 += w * __ldg(&g_xv[src*96 + u]);
                a1 += w * __ldg(&g_xv[src*96 + 32 + u]);
                a2 += w * __ldg(&g_xv[src*96 + 64 + u]);
            }
        }
    }

    if (k == 0) {
        g_aggs[n*64 + u] = a0 * INV_NB;
    } else if (k == 1) {
        g_aggs[n*64 + 32 + u] = a0 * ISQRT3F * INV_NB;
    } else if (k == 2) {
        g_aggv[n*192 +       u] = a0 * INV_NB;
        g_aggv[n*192 +  64 + u] = a1 * INV_NB;
        g_aggv[n*192 + 128 + u] = a2 * INV_NB;
    } else {
        g_aggv[n*192 +  32 + u] = a0 * INV_NB;
        g_aggv[n*192 +  96 + u] = a1 * INV_NB;
        g_aggv[n*192 + 160 + u] = a2 * INV_NB;
    }
}

// ================= launches ======================

// A: wgemm(L0)->wb0 || fctp1(L0)
__global__ void __launch_bounds__(256)
k_fusedA(const float* __restrict__ attr,
         const float* __restrict__ W0, const float* __restrict__ W1,
         const float* __restrict__ L0, const float* __restrict__ L1,
         const float* __restrict__ Wfc1, const float* __restrict__ Wfc2,
         int N, int E, int nWG, int nFC) {
    extern __shared__ float sm[];
    if ((int)blockIdx.x < nWG) wgemm_dev(sm, Wfc1, Wfc2, g_wb0, E, blockIdx.x);
    else fctp1_dev(sm, attr, W0, W1, L0, L1, N, blockIdx.x - nWG, nFC);
}

// C: wgemm(L1)->wb1 || fctp2(L0)
__global__ void __launch_bounds__(256)
k_fusedC(const float* __restrict__ attr,
         const float* __restrict__ W20, const float* __restrict__ W21,
         const float* __restrict__ Wfc1, const float* __restrict__ Wfc2,
         int N, int E, int nWG, int nFC) {
    extern __shared__ float sm[];
    if ((int)blockIdx.x < nWG) wgemm_dev(sm, Wfc1, Wfc2, g_wb1, E, blockIdx.x);
    else fctp2_dev(sm, attr, W20, W21, N, blockIdx.x - nWG, nFC);
}

__global__ void __launch_bounds__(256)
k_fctp1(const float* __restrict__ attr,
        const float* __restrict__ W0, const float* __restrict__ W1,
        const float* __restrict__ L0, const float* __restrict__ L1, int N) {
    extern __shared__ float sm[];
    fctp1_dev(sm, attr, W0, W1, L0, L1, N, blockIdx.x, gridDim.x);
}

__global__ void __launch_bounds__(256)
k_fctp2(const float* __restrict__ attr,
        const float* __restrict__ W20, const float* __restrict__ W21, int N) {
    extern __shared__ float sm[];
    fctp2_dev(sm, attr, W20, W21, N, blockIdx.x, gridDim.x);
}

// ---------------- readout + pooling ----------------
__global__ void k_zero_out(float* out) { out[threadIdx.x] = 0.0f; }

__global__ void k_read(const float* __restrict__ attr, const int* __restrict__ batch,
                       const float* __restrict__ Wread, float* __restrict__ out,
                       int N, float poolscale) {
    __shared__ float shW[2048];
    __shared__ float pool[128];
    for (int i = threadIdx.x; i < 2048; i += blockDim.x) shW[i] = Wread[i];
    if (threadIdx.x < 128) pool[threadIdx.x] = 0.0f;
    __syncthreads();
    int lane = threadIdx.x & 31;
    int wid  = blockIdx.x * (blockDim.x >> 5) + (threadIdx.x >> 5);
    int wstr = gridDim.x * (blockDim.x >> 5);
    int w = lane & 15;
    for (int n = wid; n < N; n += wstr) {
        float sl = g_s[n*32 + lane];
        float at[4] = {attr[n*4+0], attr[n*4+1], attr[n*4+2], attr[n*4+3]};
        float acc = 0.f;
        for (int u = 0; u < 32; u++) {
            float su = __shfl_sync(0xffffffffu, sl, u);
            int base = u*64 + w;
#pragma unroll
            for (int a = 0; a < 4; a++) acc += su*at[a]*shW[base + a*16];
        }
        if (lane < 16) {
            int g = batch[n];
            atomicAdd(&pool[g*16 + w], acc * NORM128 * poolscale);
        }
    }
    __syncthreads();
    if (threadIdx.x < 128) atomicAdd(&out[threadIdx.x], pool[threadIdx.x]);
}

// ---------------- launcher ----------------
extern "C" void kernel_launch(void* const* d_in, const int* in_sizes, int n_in,
                              void* d_out, int out_size) {
    const float* x    = (const float*)d_in[0];
    const float* attr = (const float*)d_in[1];
    const float* evec = (const float*)d_in[2];
    const int*   batch= (const int*)  d_in[3];
    const int*   esrc = (const int*)  d_in[4];
    const int*   edst = (const int*)  d_in[5];
    const float* Wsc0 = (const float*)d_in[6];
    const float* Wsc1 = (const float*)d_in[7];
    const float* Wl10 = (const float*)d_in[8];
    const float* Wl11 = (const float*)d_in[9];
    const float* Wfc1 = (const float*)d_in[10];
    const float* Wfc2 = (const float*)d_in[11];
    const float* Wl20 = (const float*)d_in[12];
    const float* Wl21 = (const float*)d_in[13];
    const float* Wread= (const float*)d_in[14];
    int N = in_sizes[0] / 128;
    int E = in_sizes[4];

    cudaFuncSetAttribute(k_fusedA, cudaFuncAttributeMaxDynamicSharedMemorySize, FUSED_SMEM);
    cudaFuncSetAttribute(k_fusedC, cudaFuncAttributeMaxDynamicSharedMemorySize, FUSED_SMEM);
    cudaFuncSetAttribute(k_fctp1,  cudaFuncAttributeMaxDynamicSharedMemorySize, 65536);
    cudaFuncSetAttribute(k_fctp2,  cudaFuncAttributeMaxDynamicSharedMemorySize, 65536);

    // init + CSR build (by dst) + permuted precompute
    k_init<<<(N*32 + 255) / 256, 256>>>(x, N);
    k_hist<<<(E + 255) / 256, 256>>>(edst, E);
    k_scan<<<1, SCAN_T>>>(N);
    k_fill<<<(E + 255) / 256, 256>>>(esrc, edst, E);
    k_pre_edges<<<(E + 255) / 256, 256>>>(evec, E);

    int nWG = (E + WG_TE - 1) / WG_TE;
    int nFC = 444;
    int nGB = (N + 1) / 2;

    // layer 0 + overlapped wgemm(L1)
    k_fusedA<<<nWG + nFC, 256, FUSED_SMEM>>>(attr, Wsc0, Wsc1, Wl10, Wl11,
                                             Wfc1, Wfc2, N, E, nWG, nFC);
    k_gather<0><<<nGB, 256>>>(N);
    k_fusedC<<<nWG + nFC, 256, FUSED_SMEM>>>(attr, Wl20, Wl21,
                                             Wfc1 + 640, Wfc2 + 8192, N, E, nWG, nFC);
    // layer 1 (wgemm already done -> wb1)
    k_fctp1<<<444, 256, 65536>>>(attr, Wsc0 + 4096, Wsc1 + 4096,
                                 Wl10 + 4096, Wl11 + 4096, N);
    k_gather<1><<<nGB, 256>>>(N);
    k_fctp2<<<444, 256, 65536>>>(attr, Wl20 + 8192, Wl21 + 8192, N);

    k_zero_out<<<1, 128>>>((float*)d_out);
    float poolscale = 1.0f / sqrtf((float)N / 8.0f);
    k_read<<<592, 128>>>(attr, batch, Wread, (float*)d_out, N, poolscale);
}

// round 9
// speedup vs baseline: 1.0337x; 1.0193x over previous
#include <cuda_runtime.h>
#include <cuda_bf16.h>
#include <math.h>

#define MAXN 10000
#define MAXE 320000

// ---------------- scratch (device globals; no runtime alloc) ----------------
__device__ float g_s  [MAXN*32];
__device__ float g_v  [MAXN*96];    // (N,3,32)
__device__ float g_scs[MAXN*32];
__device__ float g_scv[MAXN*96];
__device__ float g_xs [MAXN*32];
__device__ float g_xv [MAXN*96];
__device__ float g_aggs[MAXN*64];
__device__ float g_aggv[MAXN*192];
// CSR (by dst) + permuted edge data
__device__ int   g_deg   [MAXN];
__device__ int   g_cursor[MAXN];
__device__ int   g_rowstart[MAXN+1];
__device__ int   g_slot  [MAXE];
__device__ int   g_srcP  [MAXE];
__device__ float g_embP  [MAXE*10];
__device__ float g_YP    [MAXE*3];
// per-edge radial weights, bf16, double-buffered per layer
__device__ __nv_bfloat16 g_wb0[MAXE*128];
__device__ __nv_bfloat16 g_wb1[MAXE*128];

// ---------------- constants ----------------
#define SQRT3F   1.7320508075688772f
#define ISQRT3F  0.5773502691896258f
#define INV_NB   0.17677669529663687f
#define NORM128  0.08838834764831845f
#define NORM256  0.0625f
#define INVS10   0.3162277660168379f
#define C_S      0.3826834323650898f
#define C_X      0.9238795325112867f
#define PI_F     3.14159265358979f
#define WG_TE    128
#define FUSED_SMEM 73728

typedef unsigned long long ull;

// ---------------- packed f32x2 helpers ----------------
__device__ __forceinline__ ull pack2(float lo, float hi) {
    ull r;
    asm("mov.b64 %0, {%1, %2};" : "=l"(r) : "f"(lo), "f"(hi));
    return r;
}
__device__ __forceinline__ void ffma2(ull& acc, ull a, ull b) {
    asm("fma.rn.f32x2 %0, %1, %2, %0;" : "+l"(acc) : "l"(a), "l"(b));
}
__device__ __forceinline__ ull mul2r(ull a, ull b) {
    ull r;
    asm("mul.rn.f32x2 %0, %1, %2;" : "=l"(r) : "l"(a), "l"(b));
    return r;
}
__device__ __forceinline__ void mul2(ull& v, ull s) {
    asm("mul.rn.f32x2 %0, %0, %1;" : "+l"(v) : "l"(s));
}
__device__ __forceinline__ float2 unpack2(ull v) {
    float2 f;
    asm("mov.b64 {%0, %1}, %2;" : "=f"(f.x), "=f"(f.y) : "l"(v));
    return f;
}
__device__ __forceinline__ unsigned int bf16x2_of(float a, float b) {
    unsigned int r;
    asm("cvt.rn.bf16x2.f32 %0, %1, %2;" : "=r"(r) : "f"(b), "f"(a));
    return r;
}

// ---------------- init: unpack nodes + zero degree (fused) ----------------
__global__ void k_init(const float* __restrict__ x, int N) {
    int i = blockIdx.x * blockDim.x + threadIdx.x;
    if (i < N) g_deg[i] = 0;
    if (i >= N*32) return;
    int n = i >> 5, u = i & 31;
    g_s[i] = x[n*128 + u];
    g_v[n*96 +      u] = x[n*128 + 32 + u*3 + 0];
    g_v[n*96 + 32 + u] = x[n*128 + 32 + u*3 + 1];
    g_v[n*96 + 64 + u] = x[n*128 + 32 + u*3 + 2];
}
__global__ void k_hist(const int* __restrict__ edst, int E) {
    int e = blockIdx.x * blockDim.x + threadIdx.x;
    if (e < E) atomicAdd(&g_deg[edst[e]], 1);
}
#define SCAN_T 1024
__global__ void k_scan(int N) {
    __shared__ int sums[SCAN_T];
    int t = threadIdx.x;
    int IT = (N + SCAN_T - 1) / SCAN_T;
    int lo = t * IT, hi = lo + IT; if (hi > N) hi = N; if (lo > N) lo = N;
    int s = 0;
    for (int i = lo; i < hi; i++) s += g_deg[i];
    sums[t] = s;
    __syncthreads();
    for (int off = 1; off < SCAN_T; off <<= 1) {
        int v = (t >= off) ? sums[t - off] : 0;
        __syncthreads();
        sums[t] += v;
        __syncthreads();
    }
    int run = (t == 0) ? 0 : sums[t - 1];
    for (int i = lo; i < hi; i++) {
        g_rowstart[i] = run;
        g_cursor[i]   = run;
        run += g_deg[i];
    }
    if (hi == N) g_rowstart[N] = run;
}
__global__ void k_fill(const int* __restrict__ esrc, const int* __restrict__ edst, int E) {
    int e = blockIdx.x * blockDim.x + threadIdx.x;
    if (e >= E) return;
    int pos = atomicAdd(&g_cursor[edst[e]], 1);
    g_slot[e] = pos;
    g_srcP[pos] = esrc[e];
}

// ---------------- precompute edges (permuted write) ----------------
__global__ void k_pre_edges(const float* __restrict__ evec, int E) {
    int e = blockIdx.x * blockDim.x + threadIdx.x;
    if (e >= E) return;
    int p = g_slot[e];
    float vx = evec[e*3+0], vy = evec[e*3+1], vz = evec[e*3+2];
    float len = sqrtf(vx*vx + vy*vy + vz*vz);
    float inv = 1.0f / (len + 1e-9f);
    g_YP[p*3+0] = SQRT3F * vx * inv;
    g_YP[p*3+1] = SQRT3F * vy * inv;
    g_YP[p*3+2] = SQRT3F * vz * inv;
    float u = 0.5f*len - 2.0f;
    float cut;
    if (u > 0.0f)       cut = 0.0f;
    else if (u < -1.0f) cut = 1.0f;
    else                cut = (1.0f - __cosf(PI_F * u)) * 0.5f;
#pragma unroll
    for (int b = 0; b < 10; b++) {
        float c = (4.0f/9.0f) * (float)b;
        float d = (len - c) * 2.5f;
        g_embP[p*10+b] = __expf(-d*d) * cut;
    }
}

// ================= device bodies ======================

// --- fctp1: packed f32x2, interleaved weight pairs ---
__device__ void fctp1_dev(float* sm, const float* __restrict__ attr,
                          const float* __restrict__ W0, const float* __restrict__ W1,
                          const float* __restrict__ L0, const float* __restrict__ L1,
                          int N, int relBid, int nBlocks) {
    float2* sW02 = (float2*)sm;
    float2* sW12 = (float2*)(sm + 8192);
    for (int i = threadIdx.x; i < 4096; i += 256) {
        sW02[i] = make_float2(W0[i], L0[i]);
        sW12[i] = make_float2(W1[i], L1[i]);
    }
    __syncthreads();
    const ull* w02 = (const ull*)sW02;
    const ull* w12 = (const ull*)sW12;
    int lane = threadIdx.x & 31;
    int wid  = relBid * 8 + (threadIdx.x >> 5);
    int wstr = nBlocks * 8;
    for (int n = wid; n < N; n += wstr) {
        float sl = g_s[n*32 + lane];
        float v0 = g_v[n*96 + lane];
        float v1 = g_v[n*96 + 32 + lane];
        float v2 = g_v[n*96 + 64 + lane];
        ull atp[4];
#pragma unroll
        for (int a = 0; a < 4; a++) { float av = attr[n*4+a]; atp[a] = pack2(av, av); }
        ull accS = 0ull, accV0 = 0ull, accV1 = 0ull, accV2 = 0ull;
        for (int u = 0; u < 32; u++) {
            float su  = __shfl_sync(0xffffffffu, sl, u);
            float vu0 = __shfl_sync(0xffffffffu, v0, u);
            float vu1 = __shfl_sync(0xffffffffu, v1, u);
            float vu2 = __shfl_sync(0xffffffffu, v2, u);
            ull sup = pack2(su, su);
            ull v0p = pack2(vu0, vu0);
            ull v1p = pack2(vu1, vu1);
            ull v2p = pack2(vu2, vu2);
            int base = u*128 + lane;
#pragma unroll
            for (int a = 0; a < 4; a++) {
                int wi = base + a*32;
                ull wa = w02[wi];
                ull wb = w12[wi];
                ffma2(accS,  mul2r(sup, atp[a]), wa);
                ffma2(accV0, mul2r(v0p, atp[a]), wb);
                ffma2(accV1, mul2r(v1p, atp[a]), wb);
                ffma2(accV2, mul2r(v2p, atp[a]), wb);
            }
        }
        float2 fS  = unpack2(accS);
        float2 fV0 = unpack2(accV0);
        float2 fV1 = unpack2(accV1);
        float2 fV2 = unpack2(accV2);
        g_scs[n*32+lane] = fS.x*NORM128;
        g_xs [n*32+lane] = fS.y*NORM128;
        g_scv[n*96+lane]      = fV0.x*NORM128;
        g_scv[n*96+32+lane]   = fV1.x*NORM128;
        g_scv[n*96+64+lane]   = fV2.x*NORM128;
        g_xv [n*96+lane]      = fV0.y*NORM128;
        g_xv [n*96+32+lane]   = fV1.y*NORM128;
        g_xv [n*96+64+lane]   = fV2.y*NORM128;
    }
}

// --- wgemm: h = silu(emb@W1), w = h@W2/8 -> bf16 out ---
__device__ void wgemm_dev(float* sm, const float* __restrict__ Wfc1,
                          const float* __restrict__ Wfc2,
                          __nv_bfloat16* __restrict__ wout, int E, int bid) {
    float* shW1  = sm;
    float* shW2  = sm + 640;
    float* shEmb = sm + 8832;
    float* shH   = sm + 10112;   // stride 65
    int tid = threadIdx.x;
    int eg0 = bid * WG_TE;
    int nE = E - eg0; if (nE > WG_TE) nE = WG_TE;

    for (int i = tid; i < 640; i += 256) shW1[i] = Wfc1[i];
    for (int i = tid; i < 8192; i += 256) shW2[i] = Wfc2[i];
    for (int i = tid; i < WG_TE*10; i += 256) shEmb[i] = (i < nE*10) ? g_embP[eg0*10 + i] : 0.f;
    __syncthreads();

    for (int idx = tid; idx < WG_TE*64; idx += 256) {
        int e = idx >> 6, k = idx & 63;
        float acc = 0.f;
#pragma unroll
        for (int b = 0; b < 10; b++) acc += shEmb[e*10+b] * shW1[b*64+k];
        acc *= INVS10;
        shH[e*65 + k] = acc / (1.0f + __expf(-acc));
    }
    __syncthreads();

    int c0 = (tid & 15) * 8;
    int e0 = (tid >> 4) * 8;
    ull acc[8][4];
#pragma unroll
    for (int e = 0; e < 8; e++)
#pragma unroll
        for (int c = 0; c < 4; c++) acc[e][c] = 0ull;

#pragma unroll 4
    for (int k = 0; k < 64; k++) {
        const ull* Wrow = (const ull*)&shW2[k*128 + c0];
        ull w0 = Wrow[0], w1 = Wrow[1], w2 = Wrow[2], w3 = Wrow[3];
#pragma unroll
        for (int e = 0; e < 8; e++) {
            float hv = shH[(e0+e)*65 + k];
            ull hp = pack2(hv, hv);
            ffma2(acc[e][0], hp, w0);
            ffma2(acc[e][1], hp, w1);
            ffma2(acc[e][2], hp, w2);
            ffma2(acc[e][3], hp, w3);
        }
    }

    ull sc = pack2(0.125f, 0.125f);
#pragma unroll
    for (int e = 0; e < 8; e++) {
        int ge = eg0 + e0 + e;
        if (ge >= E) break;
        mul2(acc[e][0], sc); mul2(acc[e][1], sc);
        mul2(acc[e][2], sc); mul2(acc[e][3], sc);
        float2 f0 = unpack2(acc[e][0]);
        float2 f1 = unpack2(acc[e][1]);
        float2 f2 = unpack2(acc[e][2]);
        float2 f3 = unpack2(acc[e][3]);
        uint4 pk;
        pk.x = bf16x2_of(f0.x, f0.y);
        pk.y = bf16x2_of(f1.x, f1.y);
        pk.z = bf16x2_of(f2.x, f2.y);
        pk.w = bf16x2_of(f3.x, f3.y);
        *(uint4*)&wout[ge*128 + c0] = pk;
    }
}

// --- fctp2: packed f32x2 + gated state update ---
__device__ void fctp2_dev(float* sm, const float* __restrict__ attr,
                          const float* __restrict__ W20, const float* __restrict__ W21,
                          int N, int relBid, int nBlocks) {
    float2* sWp = (float2*)sm;
    for (int i = threadIdx.x; i < 8192; i += 256)
        sWp[i] = make_float2(W20[i], W21[i]);
    __syncthreads();
    const ull* wPair = (const ull*)sWp;
    int lane = threadIdx.x & 31;
    int wid  = relBid * 8 + (threadIdx.x >> 5);
    int wstr = nBlocks * 8;
    for (int n = wid; n < N; n += wstr) {
        float sa  = g_aggs[n*64 + lane],        sb  = g_aggs[n*64 + 32 + lane];
        float va0 = g_aggv[n*192 + lane],       vb0 = g_aggv[n*192 + 32 + lane];
        float va1 = g_aggv[n*192 + 64 + lane],  vb1 = g_aggv[n*192 + 96 + lane];
        float va2 = g_aggv[n*192 + 128 + lane], vb2 = g_aggv[n*192 + 160 + lane];
        ull atp[4];
#pragma unroll
        for (int a = 0; a < 4; a++) { float av = attr[n*4+a]; atp[a] = pack2(av, av); }
        ull accA = 0ull;   // {os, ov2}
        ull accB = 0ull;   // {ov0, ov1}
#pragma unroll 1
        for (int half = 0; half < 2; half++) {
            float ss  = half ? sb  : sa;
            float vv0 = half ? vb0 : va0;
            float vv1 = half ? vb1 : va1;
            float vv2 = half ? vb2 : va2;
            int uoff = half ? 32 : 0;
            for (int u = 0; u < 32; u++) {
                float su = __shfl_sync(0xffffffffu, ss,  u);
                float w0 = __shfl_sync(0xffffffffu, vv0, u);
                float w1 = __shfl_sync(0xffffffffu, vv1, u);
                float w2 = __shfl_sync(0xffffffffu, vv2, u);
                ull pA = pack2(su, w2);
                ull pB = pack2(w0, w1);
                int base = (u + uoff)*128 + lane;
#pragma unroll
                for (int a = 0; a < 4; a++) {
                    int wi = base + a*32;
                    ull wp = wPair[wi];
                    float2 wf = unpack2(wp);
                    ull wdup = pack2(wf.y, wf.y);
                    ffma2(accA, mul2r(pA, atp[a]), wp);
                    ffma2(accB, mul2r(pB, atp[a]), wdup);
                }
            }
        }
        float2 fA = unpack2(accA);
        float2 fB = unpack2(accB);
        float os  = fA.x*NORM256, ov2 = fA.y*NORM256;
        float ov0 = fB.x*NORM256, ov1 = fB.y*NORM256;
        float sn  = C_S * g_scs[n*32+lane] + C_X * os;
        float sig = 1.0f / (1.0f + __expf(-sn));
        g_s[n*32+lane] += sn * sig;
        float vn0 = C_S * g_scv[n*96+lane]      + C_X * ov0;
        float vn1 = C_S * g_scv[n*96+32+lane]   + C_X * ov1;
        float vn2 = C_S * g_scv[n*96+64+lane]   + C_X * ov2;
        g_v[n*96+lane]      += vn0 * sig;
        g_v[n*96+32+lane]   += vn1 * sig;
        g_v[n*96+64+lane]   += vn2 * sig;
    }
}

// ================= gather: dual independent edge streams per thread =========
// Two halves of the node's CSR range processed in the same loop iteration ->
// two independent srcP/w/feature load chains in flight (2x MLP vs R6).
template<int BUF>
__global__ void __launch_bounds__(256)
k_gather(int N) {
    const __nv_bfloat16* __restrict__ win = BUF ? g_wb1 : g_wb0;
    int tid = threadIdx.x;
    int n = blockIdx.x*2 + (tid >> 7);
    if (n >= N) return;
    int sub = tid & 127;
    int k = sub >> 5, u = sub & 31;
    int t0 = g_rowstart[n], t1 = g_rowstart[n+1];
    int len  = t1 - t0;
    int hlen = (len + 1) >> 1;
    int tB0  = t0 + hlen;        // stream B start; B has len - hlen <= hlen edges
    float a0 = 0.f, a1 = 0.f, a2 = 0.f;
    float b0 = 0.f, b1 = 0.f, b2 = 0.f;

    if (k == 0) {
        for (int i = 0; i < hlen; i++) {
            int eA = t0 + i, eB = tB0 + i;
            bool vB = (eB < t1);
            int sA = g_srcP[eA];
            int sB = vB ? g_srcP[eB] : 0;
            float wA = __bfloat162float(win[(size_t)eA*128 + u]);
            float wB = vB ? __bfloat162float(win[(size_t)eB*128 + u]) : 0.f;
            a0 += wA * g_xs[sA*32 + u];
            b0 += wB * g_xs[sB*32 + u];
        }
        g_aggs[n*64 + u] = (a0 + b0) * INV_NB;
    } else if (k == 1) {
        for (int i = 0; i < hlen; i++) {
            int eA = t0 + i, eB = tB0 + i;
            bool vB = (eB < t1);
            int sA = g_srcP[eA];
            int sB = vB ? g_srcP[eB] : 0;
            float wA = __bfloat162float(win[(size_t)eA*128 + 32 + u]);
            float wB = vB ? __bfloat162float(win[(size_t)eB*128 + 32 + u]) : 0.f;
            float dA = g_YP[eA*3+0]*g_xv[sA*96+u] + g_YP[eA*3+1]*g_xv[sA*96+32+u]
                     + g_YP[eA*3+2]*g_xv[sA*96+64+u];
            float dB = g_YP[eB < t1 ? eB*3+0 : 0]*g_xv[sB*96+u]
                     + g_YP[eB < t1 ? eB*3+1 : 0]*g_xv[sB*96+32+u]
                     + g_YP[eB < t1 ? eB*3+2 : 0]*g_xv[sB*96+64+u];
            a0 += wA * dA;
            b0 += wB * dB;
        }
        g_aggs[n*64 + 32 + u] = (a0 + b0) * ISQRT3F * INV_NB;
    } else if (k == 2) {
        for (int i = 0; i < hlen; i++) {
            int eA = t0 + i, eB = tB0 + i;
            bool vB = (eB < t1);
            int sA = g_srcP[eA];
            int sB = vB ? g_srcP[eB] : 0;
            float wA = __bfloat162float(win[(size_t)eA*128 + 64 + u]);
            float wB = vB ? __bfloat162float(win[(size_t)eB*128 + 64 + u]) : 0.f;
            float mA = wA * g_xs[sA*32 + u];
            float mB = wB * g_xs[sB*32 + u];
            a0 += mA * g_YP[eA*3+0];
            a1 += mA * g_YP[eA*3+1];
            a2 += mA * g_YP[eA*3+2];
            int eBs = vB ? eB : eA;
            b0 += mB * g_YP[eBs*3+0];
            b1 += mB * g_YP[eBs*3+1];
            b2 += mB * g_YP[eBs*3+2];
        }
        g_aggv[n*192 +       u] = (a0 + b0) * INV_NB;
        g_aggv[n*192 +  64 + u] = (a1 + b1) * INV_NB;
        g_aggv[n*192 + 128 + u] = (a2 + b2) * INV_NB;
    } else {
        for (int i = 0; i < hlen; i++) {
            int eA = t0 + i, eB = tB0 + i;
            bool vB = (eB < t1);
            int sA = g_srcP[eA];
            int sB = vB ? g_srcP[eB] : 0;
            float wA = __bfloat162float(win[(size_t)eA*128 + 96 + u]);
            float wB = vB ? __bfloat162float(win[(size_t)eB*128 + 96 + u]) : 0.f;
            a0 += wA * g_xv[sA*96 + u];
            a1 += wA * g_xv[sA*96 + 32 + u];
            a2 += wA * g_xv[sA*96 + 64 + u];
            b0 += wB * g_xv[sB*96 + u];
            b1 += wB * g_xv[sB*96 + 32 + u];
            b2 += wB * g_xv[sB*96 + 64 + u];
        }
        g_aggv[n*192 +  32 + u] = (a0 + b0) * INV_NB;
        g_aggv[n*192 +  96 + u] = (a1 + b1) * INV_NB;
        g_aggv[n*192 + 160 + u] = (a2 + b2) * INV_NB;
    }
}

// ================= launches ======================

// A: wgemm(L0)->wb0 || fctp1(L0)
__global__ void __launch_bounds__(256)
k_fusedA(const float* __restrict__ attr,
         const float* __restrict__ W0, const float* __restrict__ W1,
         const float* __restrict__ L0, const float* __restrict__ L1,
         const float* __restrict__ Wfc1, const float* __restrict__ Wfc2,
         int N, int E, int nWG, int nFC) {
    extern __shared__ float sm[];
    if ((int)blockIdx.x < nWG) wgemm_dev(sm, Wfc1, Wfc2, g_wb0, E, blockIdx.x);
    else fctp1_dev(sm, attr, W0, W1, L0, L1, N, blockIdx.x - nWG, nFC);
}

// C: wgemm(L1)->wb1 || (fctp2(L0) then fctp1(L1), same smem reused)
__global__ void __launch_bounds__(256)
k_fusedC(const float* __restrict__ attr,
         const float* __restrict__ W20, const float* __restrict__ W21,
         const float* __restrict__ W0b, const float* __restrict__ W1b,
         const float* __restrict__ L0b, const float* __restrict__ L1b,
         const float* __restrict__ Wfc1, const float* __restrict__ Wfc2,
         int N, int E, int nWG, int nFC) {
    extern __shared__ float sm[];
    if ((int)blockIdx.x < nWG) {
        wgemm_dev(sm, Wfc1, Wfc2, g_wb1, E, blockIdx.x);
    } else {
        int rb = blockIdx.x - nWG;
        fctp2_dev(sm, attr, W20, W21, N, rb, nFC);
        __syncthreads();   // all warps done with fctp2 smem before reload
        fctp1_dev(sm, attr, W0b, W1b, L0b, L1b, N, rb, nFC);
    }
}

__global__ void __launch_bounds__(256)
k_fctp2(const float* __restrict__ attr,
        const float* __restrict__ W20, const float* __restrict__ W21, int N) {
    extern __shared__ float sm[];
    fctp2_dev(sm, attr, W20, W21, N, blockIdx.x, gridDim.x);
}

// ---------------- readout + pooling ----------------
__global__ void k_zero_out(float* out) { out[threadIdx.x] = 0.0f; }

__global__ void k_read(const float* __restrict__ attr, const int* __restrict__ batch,
                       const float* __restrict__ Wread, float* __restrict__ out,
                       int N, float poolscale) {
    __shared__ float shW[2048];
    __shared__ float pool[128];
    for (int i = threadIdx.x; i < 2048; i += blockDim.x) shW[i] = Wread[i];
    if (threadIdx.x < 128) pool[threadIdx.x] = 0.0f;
    __syncthreads();
    int lane = threadIdx.x & 31;
    int wid  = blockIdx.x * (blockDim.x >> 5) + (threadIdx.x >> 5);
    int wstr = gridDim.x * (blockDim.x >> 5);
    int w = lane & 15;
    for (int n = wid; n < N; n += wstr) {
        float sl = g_s[n*32 + lane];
        float at[4] = {attr[n*4+0], attr[n*4+1], attr[n*4+2], attr[n*4+3]};
        float acc = 0.f;
        for (int u = 0; u < 32; u++) {
            float su = __shfl_sync(0xffffffffu, sl, u);
            int base = u*64 + w;
#pragma unroll
            for (int a = 0; a < 4; a++) acc += su*at[a]*shW[base + a*16];
        }
        if (lane < 16) {
            int g = batch[n];
            atomicAdd(&pool[g*16 + w], acc * NORM128 * poolscale);
        }
    }
    __syncthreads();
    if (threadIdx.x < 128) atomicAdd(&out[threadIdx.x], pool[threadIdx.x]);
}

// ---------------- launcher ----------------
extern "C" void kernel_launch(void* const* d_in, const int* in_sizes, int n_in,
                              void* d_out, int out_size) {
    const float* x    = (const float*)d_in[0];
    const float* attr = (const float*)d_in[1];
    const float* evec = (const float*)d_in[2];
    const int*   batch= (const int*)  d_in[3];
    const int*   esrc = (const int*)  d_in[4];
    const int*   edst = (const int*)  d_in[5];
    const float* Wsc0 = (const float*)d_in[6];
    const float* Wsc1 = (const float*)d_in[7];
    const float* Wl10 = (const float*)d_in[8];
    const float* Wl11 = (const float*)d_in[9];
    const float* Wfc1 = (const float*)d_in[10];
    const float* Wfc2 = (const float*)d_in[11];
    const float* Wl20 = (const float*)d_in[12];
    const float* Wl21 = (const float*)d_in[13];
    const float* Wread= (const float*)d_in[14];
    int N = in_sizes[0] / 128;
    int E = in_sizes[4];

    cudaFuncSetAttribute(k_fusedA, cudaFuncAttributeMaxDynamicSharedMemorySize, FUSED_SMEM);
    cudaFuncSetAttribute(k_fusedC, cudaFuncAttributeMaxDynamicSharedMemorySize, FUSED_SMEM);
    cudaFuncSetAttribute(k_fctp2,  cudaFuncAttributeMaxDynamicSharedMemorySize, 65536);

    // init + CSR build (by dst) + permuted precompute
    k_init<<<(N*32 + 255) / 256, 256>>>(x, N);
    k_hist<<<(E + 255) / 256, 256>>>(edst, E);
    k_scan<<<1, SCAN_T>>>(N);
    k_fill<<<(E + 255) / 256, 256>>>(esrc, edst, E);
    k_pre_edges<<<(E + 255) / 256, 256>>>(evec, E);

    int nWG = (E + WG_TE - 1) / WG_TE;
    int nFC = 444;
    int nGB = (N + 1) / 2;

    // layer 0 (+ hidden wgemm(L1) and fctp1(L1))
    k_fusedA<<<nWG + nFC, 256, FUSED_SMEM>>>(attr, Wsc0, Wsc1, Wl10, Wl11,
                                             Wfc1, Wfc2, N, E, nWG, nFC);
    k_gather<0><<<nGB, 256>>>(N);
    k_fusedC<<<nWG + nFC, 256, FUSED_SMEM>>>(attr, Wl20, Wl21,
                                             Wsc0 + 4096, Wsc1 + 4096,
                                             Wl10 + 4096, Wl11 + 4096,
                                             Wfc1 + 640, Wfc2 + 8192, N, E, nWG, nFC);
    // layer 1 (wgemm + fctp1 already done)
    k_gather<1><<<nGB, 256>>>(N);
    k_fctp2<<<444, 256, 65536>>>(attr, Wl20 + 8192, Wl21 + 8192, N);

    k_zero_out<<<1, 128>>>((float*)d_out);
    float poolscale = 1.0f / sqrtf((float)N / 8.0f);
    k_read<<<592, 128>>>(attr, batch, Wread, (float*)d_out, N, poolscale);
}

// round 10
// speedup vs baseline: 1.0682x; 1.0334x over previous
#include <cuda_runtime.h>
#include <cuda_bf16.h>
#include <math.h>

#define MAXN 10000
#define MAXE 320000

// ---------------- scratch (device globals; no runtime alloc) ----------------
__device__ float g_s  [MAXN*32];
__device__ float g_v  [MAXN*96];    // (N,3,32)
__device__ float g_scs[MAXN*32];
__device__ float g_scv[MAXN*96];
__device__ float g_xs [MAXN*32];
__device__ float g_xv [MAXN*96];
__device__ float g_aggs[MAXN*64];
__device__ float g_aggv[MAXN*192];
// CSR (by dst) + permuted edge data
__device__ int   g_deg   [MAXN];     // zero-initialized; restored to 0 by k_read
__device__ int   g_cursor[MAXN];
__device__ int   g_rowstart[MAXN+1];
__device__ int   g_srcP  [MAXE];
__device__ int   g_invP  [MAXE];     // permuted slot -> original edge id
__device__ float g_YP    [MAXE*3];
// per-edge radial weights, bf16, double-buffered per layer
__device__ __nv_bfloat16 g_wb0[MAXE*128];
__device__ __nv_bfloat16 g_wb1[MAXE*128];

// ---------------- constants ----------------
#define SQRT3F   1.7320508075688772f
#define ISQRT3F  0.5773502691896258f
#define INV_NB   0.17677669529663687f
#define NORM128  0.08838834764831845f
#define NORM256  0.0625f
#define INVS10   0.3162277660168379f
#define C_S      0.3826834323650898f
#define C_X      0.9238795325112867f
#define PI_F     3.14159265358979f
#define WG_TE    128
#define FUSED_SMEM 73728

typedef unsigned long long ull;

// ---------------- packed f32x2 helpers ----------------
__device__ __forceinline__ ull pack2(float lo, float hi) {
    ull r;
    asm("mov.b64 %0, {%1, %2};" : "=l"(r) : "f"(lo), "f"(hi));
    return r;
}
__device__ __forceinline__ void ffma2(ull& acc, ull a, ull b) {
    asm("fma.rn.f32x2 %0, %1, %2, %0;" : "+l"(acc) : "l"(a), "l"(b));
}
__device__ __forceinline__ ull mul2r(ull a, ull b) {
    ull r;
    asm("mul.rn.f32x2 %0, %1, %2;" : "=l"(r) : "l"(a), "l"(b));
    return r;
}
__device__ __forceinline__ void mul2(ull& v, ull s) {
    asm("mul.rn.f32x2 %0, %0, %1;" : "+l"(v) : "l"(s));
}
__device__ __forceinline__ float2 unpack2(ull v) {
    float2 f;
    asm("mov.b64 {%0, %1}, %2;" : "=f"(f.x), "=f"(f.y) : "l"(v));
    return f;
}
__device__ __forceinline__ unsigned int bf16x2_of(float a, float b) {
    unsigned int r;
    asm("cvt.rn.bf16x2.f32 %0, %1, %2;" : "=r"(r) : "f"(b), "f"(a));
    return r;
}

// ---------------- CSR build ----------------
__global__ void k_hist(const int* __restrict__ edst, int E) {
    int e = blockIdx.x * blockDim.x + threadIdx.x;
    if (e < E) atomicAdd(&g_deg[edst[e]], 1);
}
#define SCAN_T 1024
__global__ void k_scan(int N) {
    __shared__ int sums[SCAN_T];
    int t = threadIdx.x;
    int IT = (N + SCAN_T - 1) / SCAN_T;
    int lo = t * IT, hi = lo + IT; if (hi > N) hi = N; if (lo > N) lo = N;
    int s = 0;
    for (int i = lo; i < hi; i++) s += g_deg[i];
    sums[t] = s;
    __syncthreads();
    for (int off = 1; off < SCAN_T; off <<= 1) {
        int v = (t >= off) ? sums[t - off] : 0;
        __syncthreads();
        sums[t] += v;
        __syncthreads();
    }
    int run = (t == 0) ? 0 : sums[t - 1];
    for (int i = lo; i < hi; i++) {
        g_rowstart[i] = run;
        g_cursor[i]   = run;
        run += g_deg[i];
    }
    if (hi == N) g_rowstart[N] = run;
}
__global__ void k_fill(const int* __restrict__ esrc, const int* __restrict__ edst, int E) {
    int e = blockIdx.x * blockDim.x + threadIdx.x;
    if (e >= E) return;
    int pos = atomicAdd(&g_cursor[edst[e]], 1);
    g_srcP[pos] = esrc[e];
    g_invP[pos] = e;
}

// ================= device bodies ======================

// --- fctp1: packed f32x2, interleaved weight pairs.
//     If xin != nullptr, unpack x -> g_s/g_v as a side effect (layer 0). ---
__device__ void fctp1_dev(float* sm, const float* __restrict__ attr,
                          const float* __restrict__ xin,
                          const float* __restrict__ W0, const float* __restrict__ W1,
                          const float* __restrict__ L0, const float* __restrict__ L1,
                          int N, int relBid, int nBlocks) {
    float2* sW02 = (float2*)sm;
    float2* sW12 = (float2*)(sm + 8192);
    for (int i = threadIdx.x; i < 4096; i += 256) {
        sW02[i] = make_float2(W0[i], L0[i]);
        sW12[i] = make_float2(W1[i], L1[i]);
    }
    __syncthreads();
    const ull* w02 = (const ull*)sW02;
    const ull* w12 = (const ull*)sW12;
    int lane = threadIdx.x & 31;
    int wid  = relBid * 8 + (threadIdx.x >> 5);
    int wstr = nBlocks * 8;
    for (int n = wid; n < N; n += wstr) {
        float sl, v0, v1, v2;
        if (xin) {
            sl = xin[n*128 + lane];
            v0 = xin[n*128 + 32 + lane*3 + 0];
            v1 = xin[n*128 + 32 + lane*3 + 1];
            v2 = xin[n*128 + 32 + lane*3 + 2];
            g_s[n*32+lane]      = sl;
            g_v[n*96+lane]      = v0;
            g_v[n*96+32+lane]   = v1;
            g_v[n*96+64+lane]   = v2;
        } else {
            sl = g_s[n*32 + lane];
            v0 = g_v[n*96 + lane];
            v1 = g_v[n*96 + 32 + lane];
            v2 = g_v[n*96 + 64 + lane];
        }
        ull atp[4];
#pragma unroll
        for (int a = 0; a < 4; a++) { float av = attr[n*4+a]; atp[a] = pack2(av, av); }
        ull accS = 0ull, accV0 = 0ull, accV1 = 0ull, accV2 = 0ull;
        for (int u = 0; u < 32; u++) {
            float su  = __shfl_sync(0xffffffffu, sl, u);
            float vu0 = __shfl_sync(0xffffffffu, v0, u);
            float vu1 = __shfl_sync(0xffffffffu, v1, u);
            float vu2 = __shfl_sync(0xffffffffu, v2, u);
            ull sup = pack2(su, su);
            ull v0p = pack2(vu0, vu0);
            ull v1p = pack2(vu1, vu1);
            ull v2p = pack2(vu2, vu2);
            int base = u*128 + lane;
#pragma unroll
            for (int a = 0; a < 4; a++) {
                int wi = base + a*32;
                ull wa = w02[wi];
                ull wb = w12[wi];
                ffma2(accS,  mul2r(sup, atp[a]), wa);
                ffma2(accV0, mul2r(v0p, atp[a]), wb);
                ffma2(accV1, mul2r(v1p, atp[a]), wb);
                ffma2(accV2, mul2r(v2p, atp[a]), wb);
            }
        }
        float2 fS  = unpack2(accS);
        float2 fV0 = unpack2(accV0);
        float2 fV1 = unpack2(accV1);
        float2 fV2 = unpack2(accV2);
        g_scs[n*32+lane] = fS.x*NORM128;
        g_xs [n*32+lane] = fS.y*NORM128;
        g_scv[n*96+lane]      = fV0.x*NORM128;
        g_scv[n*96+32+lane]   = fV1.x*NORM128;
        g_scv[n*96+64+lane]   = fV2.x*NORM128;
        g_xv [n*96+lane]      = fV0.y*NORM128;
        g_xv [n*96+32+lane]   = fV1.y*NORM128;
        g_xv [n*96+64+lane]   = fV2.y*NORM128;
    }
}

// --- wgemm: emb from evec in-block; h = silu(emb@W1); w = h@W2/8 -> bf16 ---
__device__ void wgemm_dev(float* sm, const float* __restrict__ evec,
                          const float* __restrict__ Wfc1,
                          const float* __restrict__ Wfc2,
                          __nv_bfloat16* __restrict__ wout, int E, int bid,
                          int writeY) {
    float* shW1  = sm;
    float* shW2  = sm + 640;
    float* shEmb = sm + 8832;
    float* shH   = sm + 10112;   // stride 65
    int tid = threadIdx.x;
    int eg0 = bid * WG_TE;
    int nE = E - eg0; if (nE > WG_TE) nE = WG_TE;

    for (int i = tid; i < 640; i += 256) shW1[i] = Wfc1[i];
    for (int i = tid; i < 8192; i += 256) shW2[i] = Wfc2[i];
    // per-edge radial basis computed in-block (replaces k_pre_edges)
    if (tid < nE) {
        int p = eg0 + tid;
        int e = g_invP[p];
        float vx = evec[e*3+0], vy = evec[e*3+1], vz = evec[e*3+2];
        float len = sqrtf(vx*vx + vy*vy + vz*vz);
        if (writeY) {
            float inv = 1.0f / (len + 1e-9f);
            g_YP[p*3+0] = SQRT3F * vx * inv;
            g_YP[p*3+1] = SQRT3F * vy * inv;
            g_YP[p*3+2] = SQRT3F * vz * inv;
        }
        float uu = 0.5f*len - 2.0f;
        float cut;
        if (uu > 0.0f)       cut = 0.0f;
        else if (uu < -1.0f) cut = 1.0f;
        else                 cut = (1.0f - __cosf(PI_F * uu)) * 0.5f;
#pragma unroll
        for (int b = 0; b < 10; b++) {
            float c = (4.0f/9.0f) * (float)b;
            float d = (len - c) * 2.5f;
            shEmb[tid*10+b] = __expf(-d*d) * cut;
        }
    } else if (tid < WG_TE) {
#pragma unroll
        for (int b = 0; b < 10; b++) shEmb[tid*10+b] = 0.f;
    }
    __syncthreads();

    for (int idx = tid; idx < WG_TE*64; idx += 256) {
        int e = idx >> 6, k = idx & 63;
        float acc = 0.f;
#pragma unroll
        for (int b = 0; b < 10; b++) acc += shEmb[e*10+b] * shW1[b*64+k];
        acc *= INVS10;
        shH[e*65 + k] = acc / (1.0f + __expf(-acc));
    }
    __syncthreads();

    int c0 = (tid & 15) * 8;
    int e0 = (tid >> 4) * 8;
    ull acc[8][4];
#pragma unroll
    for (int e = 0; e < 8; e++)
#pragma unroll
        for (int c = 0; c < 4; c++) acc[e][c] = 0ull;

#pragma unroll 4
    for (int k = 0; k < 64; k++) {
        const ull* Wrow = (const ull*)&shW2[k*128 + c0];
        ull w0 = Wrow[0], w1 = Wrow[1], w2 = Wrow[2], w3 = Wrow[3];
#pragma unroll
        for (int e = 0; e < 8; e++) {
            float hv = shH[(e0+e)*65 + k];
            ull hp = pack2(hv, hv);
            ffma2(acc[e][0], hp, w0);
            ffma2(acc[e][1], hp, w1);
            ffma2(acc[e][2], hp, w2);
            ffma2(acc[e][3], hp, w3);
        }
    }

    ull sc = pack2(0.125f, 0.125f);
#pragma unroll
    for (int e = 0; e < 8; e++) {
        int ge = eg0 + e0 + e;
        if (ge >= E) break;
        mul2(acc[e][0], sc); mul2(acc[e][1], sc);
        mul2(acc[e][2], sc); mul2(acc[e][3], sc);
        float2 f0 = unpack2(acc[e][0]);
        float2 f1 = unpack2(acc[e][1]);
        float2 f2 = unpack2(acc[e][2]);
        float2 f3 = unpack2(acc[e][3]);
        uint4 pk;
        pk.x = bf16x2_of(f0.x, f0.y);
        pk.y = bf16x2_of(f1.x, f1.y);
        pk.z = bf16x2_of(f2.x, f2.y);
        pk.w = bf16x2_of(f3.x, f3.y);
        *(uint4*)&wout[ge*128 + c0] = pk;
    }
}

// --- fctp2: packed f32x2 + gated state update ---
__device__ void fctp2_dev(float* sm, const float* __restrict__ attr,
                          const float* __restrict__ W20, const float* __restrict__ W21,
                          int N, int relBid, int nBlocks) {
    float2* sWp = (float2*)sm;
    for (int i = threadIdx.x; i < 8192; i += 256)
        sWp[i] = make_float2(W20[i], W21[i]);
    __syncthreads();
    const ull* wPair = (const ull*)sWp;
    int lane = threadIdx.x & 31;
    int wid  = relBid * 8 + (threadIdx.x >> 5);
    int wstr = nBlocks * 8;
    for (int n = wid; n < N; n += wstr) {
        float sa  = g_aggs[n*64 + lane],        sb  = g_aggs[n*64 + 32 + lane];
        float va0 = g_aggv[n*192 + lane],       vb0 = g_aggv[n*192 + 32 + lane];
        float va1 = g_aggv[n*192 + 64 + lane],  vb1 = g_aggv[n*192 + 96 + lane];
        float va2 = g_aggv[n*192 + 128 + lane], vb2 = g_aggv[n*192 + 160 + lane];
        ull atp[4];
#pragma unroll
        for (int a = 0; a < 4; a++) { float av = attr[n*4+a]; atp[a] = pack2(av, av); }
        ull accA = 0ull;   // {os, ov2}
        ull accB = 0ull;   // {ov0, ov1}
#pragma unroll 1
        for (int half = 0; half < 2; half++) {
            float ss  = half ? sb  : sa;
            float vv0 = half ? vb0 : va0;
            float vv1 = half ? vb1 : va1;
            float vv2 = half ? vb2 : va2;
            int uoff = half ? 32 : 0;
            for (int u = 0; u < 32; u++) {
                float su = __shfl_sync(0xffffffffu, ss,  u);
                float w0 = __shfl_sync(0xffffffffu, vv0, u);
                float w1 = __shfl_sync(0xffffffffu, vv1, u);
                float w2 = __shfl_sync(0xffffffffu, vv2, u);
                ull pA = pack2(su, w2);
                ull pB = pack2(w0, w1);
                int base = (u + uoff)*128 + lane;
#pragma unroll
                for (int a = 0; a < 4; a++) {
                    int wi = base + a*32;
                    ull wp = wPair[wi];
                    float2 wf = unpack2(wp);
                    ull wdup = pack2(wf.y, wf.y);
                    ffma2(accA, mul2r(pA, atp[a]), wp);
                    ffma2(accB, mul2r(pB, atp[a]), wdup);
                }
            }
        }
        float2 fA = unpack2(accA);
        float2 fB = unpack2(accB);
        float os  = fA.x*NORM256, ov2 = fA.y*NORM256;
        float ov0 = fB.x*NORM256, ov1 = fB.y*NORM256;
        float sn  = C_S * g_scs[n*32+lane] + C_X * os;
        float sig = 1.0f / (1.0f + __expf(-sn));
        g_s[n*32+lane] += sn * sig;
        float vn0 = C_S * g_scv[n*96+lane]      + C_X * ov0;
        float vn1 = C_S * g_scv[n*96+32+lane]   + C_X * ov1;
        float vn2 = C_S * g_scv[n*96+64+lane]   + C_X * ov2;
        g_v[n*96+lane]      += vn0 * sig;
        g_v[n*96+32+lane]   += vn1 * sig;
        g_v[n*96+64+lane]   += vn2 * sig;
    }
}

// ================= gather: dual independent edge streams per thread =========
template<int BUF>
__global__ void __launch_bounds__(256)
k_gather(int N) {
    const __nv_bfloat16* __restrict__ win = BUF ? g_wb1 : g_wb0;
    int tid = threadIdx.x;
    int n = blockIdx.x*2 + (tid >> 7);
    if (n >= N) return;
    int sub = tid & 127;
    int k = sub >> 5, u = sub & 31;
    int t0 = g_rowstart[n], t1 = g_rowstart[n+1];
    int len  = t1 - t0;
    int hlen = (len + 1) >> 1;
    int tB0  = t0 + hlen;
    float a0 = 0.f, a1 = 0.f, a2 = 0.f;
    float b0 = 0.f, b1 = 0.f, b2 = 0.f;

    if (k == 0) {
        for (int i = 0; i < hlen; i++) {
            int eA = t0 + i, eB = tB0 + i;
            bool vB = (eB < t1);
            int sA = g_srcP[eA];
            int sB = vB ? g_srcP[eB] : 0;
            float wA = __bfloat162float(win[(size_t)eA*128 + u]);
            float wB = vB ? __bfloat162float(win[(size_t)eB*128 + u]) : 0.f;
            a0 += wA * g_xs[sA*32 + u];
            b0 += wB * g_xs[sB*32 + u];
        }
        g_aggs[n*64 + u] = (a0 + b0) * INV_NB;
    } else if (k == 1) {
        for (int i = 0; i < hlen; i++) {
            int eA = t0 + i, eB = tB0 + i;
            bool vB = (eB < t1);
            int sA = g_srcP[eA];
            int sB = vB ? g_srcP[eB] : 0;
            float wA = __bfloat162float(win[(size_t)eA*128 + 32 + u]);
            float wB = vB ? __bfloat162float(win[(size_t)eB*128 + 32 + u]) : 0.f;
            float dA = g_YP[eA*3+0]*g_xv[sA*96+u] + g_YP[eA*3+1]*g_xv[sA*96+32+u]
                     + g_YP[eA*3+2]*g_xv[sA*96+64+u];
            float dB = g_YP[eB < t1 ? eB*3+0 : 0]*g_xv[sB*96+u]
                     + g_YP[eB < t1 ? eB*3+1 : 0]*g_xv[sB*96+32+u]
                     + g_YP[eB < t1 ? eB*3+2 : 0]*g_xv[sB*96+64+u];
            a0 += wA * dA;
            b0 += wB * dB;
        }
        g_aggs[n*64 + 32 + u] = (a0 + b0) * ISQRT3F * INV_NB;
    } else if (k == 2) {
        for (int i = 0; i < hlen; i++) {
            int eA = t0 + i, eB = tB0 + i;
            bool vB = (eB < t1);
            int sA = g_srcP[eA];
            int sB = vB ? g_srcP[eB] : 0;
            float wA = __bfloat162float(win[(size_t)eA*128 + 64 + u]);
            float wB = vB ? __bfloat162float(win[(size_t)eB*128 + 64 + u]) : 0.f;
            float mA = wA * g_xs[sA*32 + u];
            float mB = wB * g_xs[sB*32 + u];
            a0 += mA * g_YP[eA*3+0];
            a1 += mA * g_YP[eA*3+1];
            a2 += mA * g_YP[eA*3+2];
            int eBs = vB ? eB : eA;
            b0 += mB * g_YP[eBs*3+0];
            b1 += mB * g_YP[eBs*3+1];
            b2 += mB * g_YP[eBs*3+2];
        }
        g_aggv[n*192 +       u] = (a0 + b0) * INV_NB;
        g_aggv[n*192 +  64 + u] = (a1 + b1) * INV_NB;
        g_aggv[n*192 + 128 + u] = (a2 + b2) * INV_NB;
    } else {
        for (int i = 0; i < hlen; i++) {
            int eA = t0 + i, eB = tB0 + i;
            bool vB = (eB < t1);
            int sA = g_srcP[eA];
            int sB = vB ? g_srcP[eB] : 0;
            float wA = __bfloat162float(win[(size_t)eA*128 + 96 + u]);
            float wB = vB ? __bfloat162float(win[(size_t)eB*128 + 96 + u]) : 0.f;
            a0 += wA * g_xv[sA*96 + u];
            a1 += wA * g_xv[sA*96 + 32 + u];
            a2 += wA * g_xv[sA*96 + 64 + u];
            b0 += wB * g_xv[sB*96 + u];
            b1 += wB * g_xv[sB*96 + 32 + u];
            b2 += wB * g_xv[sB*96 + 64 + u];
        }
        g_aggv[n*192 +  32 + u] = (a0 + b0) * INV_NB;
        g_aggv[n*192 +  96 + u] = (a1 + b1) * INV_NB;
        g_aggv[n*192 + 160 + u] = (a2 + b2) * INV_NB;
    }
}

// ================= launches ======================

// A: wgemm(L0)->wb0 (computes emb + writes YP) || fctp1(L0) (unpacks x)
__global__ void __launch_bounds__(256)
k_fusedA(const float* __restrict__ attr, const float* __restrict__ x,
         const float* __restrict__ evec,
         const float* __restrict__ W0, const float* __restrict__ W1,
         const float* __restrict__ L0, const float* __restrict__ L1,
         const float* __restrict__ Wfc1, const float* __restrict__ Wfc2,
         int N, int E, int nWG, int nFC) {
    extern __shared__ float sm[];
    if ((int)blockIdx.x < nWG) wgemm_dev(sm, evec, Wfc1, Wfc2, g_wb0, E, blockIdx.x, 1);
    else fctp1_dev(sm, attr, x, W0, W1, L0, L1, N, blockIdx.x - nWG, nFC);
}

// C: wgemm(L1)->wb1 || (fctp2(L0) then fctp1(L1), same smem reused)
__global__ void __launch_bounds__(256)
k_fusedC(const float* __restrict__ attr, const float* __restrict__ evec,
         const float* __restrict__ W20, const float* __restrict__ W21,
         const float* __restrict__ W0b, const float* __restrict__ W1b,
         const float* __restrict__ L0b, const float* __restrict__ L1b,
         const float* __restrict__ Wfc1, const float* __restrict__ Wfc2,
         int N, int E, int nWG, int nFC) {
    extern __shared__ float sm[];
    if ((int)blockIdx.x < nWG) {
        wgemm_dev(sm, evec, Wfc1, Wfc2, g_wb1, E, blockIdx.x, 0);
    } else {
        int rb = blockIdx.x - nWG;
        fctp2_dev(sm, attr, W20, W21, N, rb, nFC);
        __syncthreads();
        fctp1_dev(sm, attr, nullptr, W0b, W1b, L0b, L1b, N, rb, nFC);
    }
}

__global__ void __launch_bounds__(256)
k_fctp2(const float* __restrict__ attr,
        const float* __restrict__ W20, const float* __restrict__ W21, int N) {
    extern __shared__ float sm[];
    fctp2_dev(sm, attr, W20, W21, N, blockIdx.x, gridDim.x);
}

// ---------------- readout + pooling (+ restores g_deg=0 for next call) ------
__global__ void k_zero_out(float* out) { out[threadIdx.x] = 0.0f; }

__global__ void k_read(const float* __restrict__ attr, const int* __restrict__ batch,
                       const float* __restrict__ Wread, float* __restrict__ out,
                       int N, float poolscale) {
    __shared__ float shW[2048];
    __shared__ float pool[128];
    // restore degree histogram to zero for the next graph replay
    for (int i = blockIdx.x * blockDim.x + threadIdx.x; i < N;
         i += gridDim.x * blockDim.x)
        g_deg[i] = 0;
    for (int i = threadIdx.x; i < 2048; i += blockDim.x) shW[i] = Wread[i];
    if (threadIdx.x < 128) pool[threadIdx.x] = 0.0f;
    __syncthreads();
    int lane = threadIdx.x & 31;
    int wid  = blockIdx.x * (blockDim.x >> 5) + (threadIdx.x >> 5);
    int wstr = gridDim.x * (blockDim.x >> 5);
    int w = lane & 15;
    for (int n = wid; n < N; n += wstr) {
        float sl = g_s[n*32 + lane];
        float at[4] = {attr[n*4+0], attr[n*4+1], attr[n*4+2], attr[n*4+3]};
        float acc = 0.f;
        for (int u = 0; u < 32; u++) {
            float su = __shfl_sync(0xffffffffu, sl, u);
            int base = u*64 + w;
#pragma unroll
            for (int a = 0; a < 4; a++) acc += su*at[a]*shW[base + a*16];
        }
        if (lane < 16) {
            int g = batch[n];
            atomicAdd(&pool[g*16 + w], acc * NORM128 * poolscale);
        }
    }
    __syncthreads();
    if (threadIdx.x < 128) atomicAdd(&out[threadIdx.x], pool[threadIdx.x]);
}

// ---------------- launcher ----------------
extern "C" void kernel_launch(void* const* d_in, const int* in_sizes, int n_in,
                              void* d_out, int out_size) {
    const float* x    = (const float*)d_in[0];
    const float* attr = (const float*)d_in[1];
    const float* evec = (const float*)d_in[2];
    const int*   batch= (const int*)  d_in[3];
    const int*   esrc = (const int*)  d_in[4];
    const int*   edst = (const int*)  d_in[5];
    const float* Wsc0 = (const float*)d_in[6];
    const float* Wsc1 = (const float*)d_in[7];
    const float* Wl10 = (const float*)d_in[8];
    const float* Wl11 = (const float*)d_in[9];
    const float* Wfc1 = (const float*)d_in[10];
    const float* Wfc2 = (const float*)d_in[11];
    const float* Wl20 = (const float*)d_in[12];
    const float* Wl21 = (const float*)d_in[13];
    const float* Wread= (const float*)d_in[14];
    int N = in_sizes[0] / 128;
    int E = in_sizes[4];

    cudaFuncSetAttribute(k_fusedA, cudaFuncAttributeMaxDynamicSharedMemorySize, FUSED_SMEM);
    cudaFuncSetAttribute(k_fusedC, cudaFuncAttributeMaxDynamicSharedMemorySize, FUSED_SMEM);
    cudaFuncSetAttribute(k_fctp2,  cudaFuncAttributeMaxDynamicSharedMemorySize, 65536);

    int nWG = (E + WG_TE - 1) / WG_TE;
    int nFC = 444;
    int nGB = (N + 1) / 2;

    // CSR build (g_deg was zeroed by the previous call's k_read / static init)
    k_hist<<<(E + 255) / 256, 256>>>(edst, E);                 // launch 1
    k_scan<<<1, SCAN_T>>>(N);                                  // launch 2
    k_fill<<<(E + 255) / 256, 256>>>(esrc, edst, E);           // launch 3

    // layer 0 (+ hidden wgemm(L1) and fctp1(L1))
    k_fusedA<<<nWG + nFC, 256, FUSED_SMEM>>>(attr, x, evec,    // launch 4 (profiled)
                                             Wsc0, Wsc1, Wl10, Wl11,
                                             Wfc1, Wfc2, N, E, nWG, nFC);
    k_gather<0><<<nGB, 256>>>(N);
    k_fusedC<<<nWG + nFC, 256, FUSED_SMEM>>>(attr, evec, Wl20, Wl21,
                                             Wsc0 + 4096, Wsc1 + 4096,
                                             Wl10 + 4096, Wl11 + 4096,
                                             Wfc1 + 640, Wfc2 + 8192, N, E, nWG, nFC);
    // layer 1 (wgemm + fctp1 already done)
    k_gather<1><<<nGB, 256>>>(N);
    k_fctp2<<<444, 256, 65536>>>(attr, Wl20 + 8192, Wl21 + 8192, N);

    k_zero_out<<<1, 128>>>((float*)d_out);
    float poolscale = 1.0f / sqrtf((float)N / 8.0f);
    k_read<<<592, 128>>>(attr, batch, Wread, (float*)d_out, N, poolscale);
}